// round 7
// baseline (speedup 1.0000x reference)
#include <cuda_runtime.h>
#include <cstdint>

// ---------------------------------------------------------------------------
// EfficientSelfAttention (PVT spatial-reduction attention), fp32.
//   B=8, N=16384 (128x128), C=64, heads=1, SR=8 -> Nr=256.
//
//   xr   = conv8x8s8(x) + sr_b
//   y    = LN(xr)
//   Kt   = (K @ q_w) * SCALE ; kb = (K @ q_b) * SCALE   (fold q-proj)
//   Wv   = V @ proj_w.T                                 (fold out-proj)
//   s_nj = x_n . Kt_j + kb_j ; p = exp(s) (unnormalized), den = row-sum
//   out  = (p @ Wv)/den + proj_b
//
// Attention = cooperative register-tiled FFMA2 GEMM (256 thr / 128 rows),
// chunked over j (4 x 64) with P staged in smem between the two GEMM passes.
// ---------------------------------------------------------------------------

#define BATCH 8
#define NQ    16384
#define C     64
#define NR    256
#define SCALEF 0.125f
#define RS 68   // smem row stride in floats (bank-conflict padding)

// ------------------------- scratch (device globals) ------------------------
__device__ float g_wT[64 * 64 * 64];     // conv weights [kh*8+kw][ic][oc]
__device__ float g_xr[BATCH * NR * C];   // conv output (pre-LN)
__device__ float g_Kt[BATCH * NR * C];   // folded+scaled K  [b][j][c]
__device__ float g_kb[BATCH * NR];       // folded+scaled bias
__device__ float g_Wv[BATCH * NR * C];   // folded V         [b][j][c]

// ------------------------- f32x2 packed helpers ----------------------------
__device__ __forceinline__ unsigned long long pack2(float lo, float hi) {
    unsigned long long r;
    asm("mov.b64 %0, {%1, %2};" : "=l"(r) : "f"(lo), "f"(hi));
    return r;
}
__device__ __forceinline__ void unpack2(unsigned long long v, float& lo, float& hi) {
    asm("mov.b64 {%0, %1}, %2;" : "=f"(lo), "=f"(hi) : "l"(v));
}
__device__ __forceinline__ unsigned long long fma2(unsigned long long a,
                                                   unsigned long long b,
                                                   unsigned long long c) {
    unsigned long long d;
    asm("fma.rn.f32x2 %0, %1, %2, %3;" : "=l"(d) : "l"(a), "l"(b), "l"(c));
    return d;
}

// ---------------------------------------------------------------------------
// Kernel 1: transpose conv weights OIHW -> [kh][kw][ic][oc].
// ---------------------------------------------------------------------------
__global__ void prep_w_kernel(const float* __restrict__ sr_w) {
    int i = blockIdx.x * blockDim.x + threadIdx.x;
    int oc = i & 63;
    int ic = (i >> 6) & 63;
    int kw = (i >> 12) & 7;
    int kh = (i >> 15) & 7;
    g_wT[i] = sr_w[((oc * 64 + ic) * 8 + kh) * 8 + kw];
}

// ---------------------------------------------------------------------------
// Kernel 2: 8x8 stride-8 conv + bias. Grid (16, 8), 256 threads.
// ---------------------------------------------------------------------------
__global__ void conv_kernel(const float* __restrict__ x,
                            const float* __restrict__ sr_b) {
    __shared__ float xs[8192];
    __shared__ float ws[4096];

    const int oh = blockIdx.x;
    const int b  = blockIdx.y;
    const int t  = threadIdx.x;
    const int ow = t >> 4;
    const int g  = t & 15;

    float a0 = 0.f, a1 = 0.f, a2 = 0.f, a3 = 0.f;

    for (int kh = 0; kh < 8; kh++) {
        __syncthreads();
        const float4* src =
            (const float4*)(x + ((size_t)(b * NQ + (oh * 8 + kh) * 128)) * C);
        float4* xs4 = (float4*)xs;
        #pragma unroll
        for (int i = t; i < 2048; i += 256) xs4[i] = src[i];

        for (int kw = 0; kw < 8; kw++) {
            __syncthreads();
            const float4* wsrc = (const float4*)(g_wT + (kh * 8 + kw) * 4096);
            float4* ws4 = (float4*)ws;
            #pragma unroll
            for (int i = t; i < 1024; i += 256) ws4[i] = wsrc[i];
            __syncthreads();

            const float* xp = xs + (ow * 8 + kw) * 64;
            const float4* wp = (const float4*)ws + g;
            #pragma unroll 8
            for (int ic = 0; ic < 64; ic++) {
                float xv = xp[ic];
                float4 w4 = wp[ic * 16];
                a0 = fmaf(xv, w4.x, a0);
                a1 = fmaf(xv, w4.y, a1);
                a2 = fmaf(xv, w4.z, a2);
                a3 = fmaf(xv, w4.w, a3);
            }
        }
    }

    int oc = 4 * g;
    float4 o;
    o.x = a0 + sr_b[oc + 0];
    o.y = a1 + sr_b[oc + 1];
    o.z = a2 + sr_b[oc + 2];
    o.w = a3 + sr_b[oc + 3];
    size_t row = (size_t)b * NR + oh * 16 + ow;
    ((float4*)(g_xr + row * C))[g] = o;
}

// ---------------------------------------------------------------------------
// Kernel 3: LN + KV proj + fold. Writes g_Kt, g_kb, g_Wv.
// ---------------------------------------------------------------------------
__global__ void ln_fold_kernel(const float* __restrict__ ln_g,
                               const float* __restrict__ ln_b,
                               const float* __restrict__ q_w,
                               const float* __restrict__ q_b,
                               const float* __restrict__ kv_w,
                               const float* __restrict__ kv_b,
                               const float* __restrict__ proj_w) {
    __shared__ float sy[64], sk[64], sv[64], red[4];
    const int t = threadIdx.x;

    for (int rr = 0; rr < 8; rr++) {
        int row = blockIdx.x * 8 + rr;  // 0..2047
        float v = g_xr[row * 64 + t];

        float s = v, sq = v * v;
        #pragma unroll
        for (int off = 16; off > 0; off >>= 1) {
            s  += __shfl_xor_sync(0xffffffffu, s, off);
            sq += __shfl_xor_sync(0xffffffffu, sq, off);
        }
        if ((t & 31) == 0) { red[t >> 5] = s; red[2 + (t >> 5)] = sq; }
        __syncthreads();
        float mu  = (red[0] + red[1]) * (1.0f / 64.0f);
        float var = (red[2] + red[3]) * (1.0f / 64.0f) - mu * mu;
        float y   = (v - mu) * rsqrtf(var + 1e-5f) * ln_g[t] + ln_b[t];
        sy[t] = y;
        __syncthreads();

        float kd = kv_b[t], vd = kv_b[64 + t];
        const float* kwk = kv_w + t * 64;
        const float* kwv = kv_w + (64 + t) * 64;
        #pragma unroll 8
        for (int c = 0; c < 64; c++) {
            kd = fmaf(sy[c], kwk[c], kd);
            vd = fmaf(sy[c], kwv[c], vd);
        }
        sk[t] = kd; sv[t] = vd;
        __syncthreads();

        float kt = 0.f, wv = 0.f;
        const float* pw = proj_w + t * 64;
        #pragma unroll 8
        for (int d = 0; d < 64; d++) {
            kt = fmaf(sk[d], q_w[d * 64 + t], kt);
            wv = fmaf(sv[d], pw[d], wv);
        }
        g_Kt[row * 64 + t] = kt * SCALEF;
        g_Wv[row * 64 + t] = wv;
        if (t == 0) {
            float kb = 0.f;
            for (int d = 0; d < 64; d++) kb = fmaf(q_b[d], sk[d], kb);
            g_kb[row] = kb * SCALEF;
        }
        __syncthreads();
    }
}

// ---------------------------------------------------------------------------
// Kernel 4: cooperative attention. CTA = 128 query rows, 256 threads.
// Thread (jg = t&7, rg = t>>3) owns rows {rg+32i} and, per chunk,
//   pass1: j-columns {c*64 + 8p + jg}, pass2: channels {8*jg .. 8*jg+7}.
// Smem (floats): sX[128*68] sKt[256*68] sWv[256*68] sP[128*68] kb[256] pb[64]
// ---------------------------------------------------------------------------
#define ATTN_SMEM_FLOATS (8704 + 17408 + 17408 + 8704 + 256 + 64)
#define ATTN_SMEM_BYTES  (ATTN_SMEM_FLOATS * 4)

__global__ __launch_bounds__(256, 1)
void attn_kernel(const float* __restrict__ x,
                 const float* __restrict__ proj_b,
                 float* __restrict__ out) {
    extern __shared__ float sm[];
    float* sX  = sm;                  // 128*68
    float* sKt = sm + 8704;           // 256*68
    float* sWv = sm + 26112;          // 256*68
    float* sP  = sm + 43520;          // 128*68
    float* skb = sm + 52224;          // 256
    float* spb = sm + 52480;          // 64

    const int t    = threadIdx.x;
    const int tile = blockIdx.x;      // 0..127
    const int b    = blockIdx.y;      // 0..7

    // ---- stage tiles ----
    {
        const float4* gx =
            (const float4*)(x + ((size_t)b * NQ + (size_t)tile * 128) * C);
        #pragma unroll
        for (int i = 0; i < 8; i++) {
            int e = t + i * 256;                 // 0..2047
            float4 v = gx[e];
            *(float4*)&sX[(e >> 4) * RS + (e & 15) * 4] = v;
        }
        const float4* gk = (const float4*)(g_Kt + (size_t)b * NR * C);
        const float4* gw = (const float4*)(g_Wv + (size_t)b * NR * C);
        #pragma unroll
        for (int i = 0; i < 16; i++) {
            int e = t + i * 256;                 // 0..4095
            float4 kv = gk[e];
            *(float4*)&sKt[(e >> 4) * RS + (e & 15) * 4] = kv;
            float4 wv = gw[e];
            *(float4*)&sWv[(e >> 4) * RS + (e & 15) * 4] = wv;
        }
        skb[t] = g_kb[b * NR + t];
        if (t < 64) spb[t] = proj_b[t];
    }
    __syncthreads();

    const int jg = t & 7;
    const int rg = t >> 3;

    unsigned long long acc2[4][4];
    #pragma unroll
    for (int i = 0; i < 4; i++)
        #pragma unroll
        for (int q = 0; q < 4; q++) acc2[i][q] = 0ull;
    float dsum[4] = {0.f, 0.f, 0.f, 0.f};

    #pragma unroll 1
    for (int c = 0; c < 4; c++) {
        const int c64 = c * 64;

        // ===== pass 1: S-chunk = X @ Kt^T, exp, store P =====
        unsigned long long s2[4][8];
        #pragma unroll
        for (int i = 0; i < 4; i++)
            #pragma unroll
            for (int p = 0; p < 8; p++) s2[i][p] = 0ull;

        #pragma unroll 2
        for (int k = 0; k < 64; k += 4) {
            unsigned long long xlo[4], xhi[4];
            #pragma unroll
            for (int i = 0; i < 4; i++) {
                float4 v = *(const float4*)&sX[(rg + 32 * i) * RS + k];
                xlo[i] = pack2(v.x, v.y);
                xhi[i] = pack2(v.z, v.w);
            }
            #pragma unroll
            for (int p = 0; p < 8; p++) {
                float4 kv = *(const float4*)&sKt[(c64 + 8 * p + jg) * RS + k];
                unsigned long long klo = pack2(kv.x, kv.y);
                unsigned long long khi = pack2(kv.z, kv.w);
                #pragma unroll
                for (int i = 0; i < 4; i++) {
                    s2[i][p] = fma2(xlo[i], klo, s2[i][p]);
                    s2[i][p] = fma2(xhi[i], khi, s2[i][p]);
                }
            }
        }
        #pragma unroll
        for (int p = 0; p < 8; p++) {
            float kbv = skb[c64 + 8 * p + jg];
            #pragma unroll
            for (int i = 0; i < 4; i++) {
                float a, bb;
                unpack2(s2[i][p], a, bb);
                float e = __expf(a + bb + kbv);
                dsum[i] += e;
                sP[(rg + 32 * i) * RS + 8 * p + jg] = e;
            }
        }
        __syncthreads();

        // ===== pass 2: acc += P-chunk @ Wv-chunk =====
        #pragma unroll 2
        for (int jj = 0; jj < 64; jj += 2) {
            const float* w0 = &sWv[(c64 + jj) * RS + jg * 8];
            const float* w1 = w0 + RS;
            float4 wa0 = *(const float4*)w0;
            float4 wb0 = *(const float4*)(w0 + 4);
            float4 wa1 = *(const float4*)w1;
            float4 wb1 = *(const float4*)(w1 + 4);
            unsigned long long w0q0 = pack2(wa0.x, wa0.y);
            unsigned long long w0q1 = pack2(wa0.z, wa0.w);
            unsigned long long w0q2 = pack2(wb0.x, wb0.y);
            unsigned long long w0q3 = pack2(wb0.z, wb0.w);
            unsigned long long w1q0 = pack2(wa1.x, wa1.y);
            unsigned long long w1q1 = pack2(wa1.z, wa1.w);
            unsigned long long w1q2 = pack2(wb1.x, wb1.y);
            unsigned long long w1q3 = pack2(wb1.z, wb1.w);
            #pragma unroll
            for (int i = 0; i < 4; i++) {
                float2 pv = *(const float2*)&sP[(rg + 32 * i) * RS + jj];
                unsigned long long p0 = pack2(pv.x, pv.x);
                unsigned long long p1 = pack2(pv.y, pv.y);
                acc2[i][0] = fma2(p0, w0q0, acc2[i][0]);
                acc2[i][1] = fma2(p0, w0q1, acc2[i][1]);
                acc2[i][2] = fma2(p0, w0q2, acc2[i][2]);
                acc2[i][3] = fma2(p0, w0q3, acc2[i][3]);
                acc2[i][0] = fma2(p1, w1q0, acc2[i][0]);
                acc2[i][1] = fma2(p1, w1q1, acc2[i][1]);
                acc2[i][2] = fma2(p1, w1q2, acc2[i][2]);
                acc2[i][3] = fma2(p1, w1q3, acc2[i][3]);
            }
        }
        __syncthreads();  // P buffer reused next chunk
    }

    // ---- den: reduce across the 8 j-groups (lanes sharing rg) ----
    #pragma unroll
    for (int i = 0; i < 4; i++) {
        #pragma unroll
        for (int off = 1; off < 8; off <<= 1)
            dsum[i] += __shfl_xor_sync(0xffffffffu, dsum[i], off);
    }

    // ---- epilogue: out = acc/den + proj_b ----
    #pragma unroll
    for (int i = 0; i < 4; i++) {
        float inv = 1.0f / dsum[i];
        float o0, o1, o2, o3, o4, o5, o6, o7;
        unpack2(acc2[i][0], o0, o1);
        unpack2(acc2[i][1], o2, o3);
        unpack2(acc2[i][2], o4, o5);
        unpack2(acc2[i][3], o6, o7);
        const float* pb = spb + jg * 8;
        float4* orow = (float4*)(out +
            ((size_t)b * NQ + (size_t)tile * 128 + rg + 32 * i) * C + jg * 8);
        float4 r0, r1;
        r0.x = fmaf(o0, inv, pb[0]);
        r0.y = fmaf(o1, inv, pb[1]);
        r0.z = fmaf(o2, inv, pb[2]);
        r0.w = fmaf(o3, inv, pb[3]);
        r1.x = fmaf(o4, inv, pb[4]);
        r1.y = fmaf(o5, inv, pb[5]);
        r1.z = fmaf(o6, inv, pb[6]);
        r1.w = fmaf(o7, inv, pb[7]);
        orow[0] = r0;
        orow[1] = r1;
    }
}

// ---------------------------------------------------------------------------
extern "C" void kernel_launch(void* const* d_in, const int* in_sizes, int n_in,
                              void* d_out, int out_size) {
    const float* x      = (const float*)d_in[0];
    const float* sr_w   = (const float*)d_in[1];
    const float* sr_b   = (const float*)d_in[2];
    const float* ln_g   = (const float*)d_in[3];
    const float* ln_b   = (const float*)d_in[4];
    const float* q_w    = (const float*)d_in[5];
    const float* q_b    = (const float*)d_in[6];
    const float* kv_w   = (const float*)d_in[7];
    const float* kv_b   = (const float*)d_in[8];
    const float* proj_w = (const float*)d_in[9];
    const float* proj_b = (const float*)d_in[10];
    float* out = (float*)d_out;

    static bool attr_set = false;
    if (!attr_set) {
        cudaFuncSetAttribute(attn_kernel,
                             cudaFuncAttributeMaxDynamicSharedMemorySize,
                             ATTN_SMEM_BYTES);
        attr_set = true;
    }

    prep_w_kernel<<<256, 1024>>>(sr_w);
    conv_kernel<<<dim3(16, 8), 256>>>(x, sr_b);
    ln_fold_kernel<<<256, 64>>>(ln_g, ln_b, q_w, q_b, kv_w, kv_b, proj_w);
    attn_kernel<<<dim3(128, 8), 256, ATTN_SMEM_BYTES>>>(x, proj_b, out);
}

// round 10
// speedup vs baseline: 1.5705x; 1.5705x over previous
#include <cuda_runtime.h>
#include <cstdint>

// ---------------------------------------------------------------------------
// EfficientSelfAttention (PVT spatial-reduction attention), fp32.
//   B=8, N=16384 (128x128), C=64, heads=1, SR=8 -> Nr=256.
//
//   xr   = conv8x8s8(x) + sr_b
//   y    = LN(xr)
//   Kt   = (K @ q_w) * SCALE ; kb = (K @ q_b) * SCALE   (fold q-proj)
//   Wv   = V @ proj_w.T                                 (fold out-proj)
//   s_nj = x_n . Kt_j + kb_j ; p = exp(s) (unnormalized), den = row-sum
//   out  = (p @ Wv)/den + proj_b
//
// Attention: 64-row tiles, 128 threads, j-chunked (4 x 64); Kt/Wv chunks
// streamed gmem->smem so 3 CTAs fit per SM (smem 70.9KB, regs capped 170).
// ---------------------------------------------------------------------------

#define BATCH 8
#define NQ    16384
#define C     64
#define NR    256
#define SCALEF 0.125f
#define RS 68   // smem row stride in floats (bank-conflict padding)

// ------------------------- scratch (device globals) ------------------------
__device__ float g_wT[64 * 64 * 64];     // conv weights [kh*8+kw][ic][oc]
__device__ float g_xr[BATCH * NR * C];   // conv output (pre-LN)
__device__ float g_Kt[BATCH * NR * C];   // folded+scaled K  [b][j][c]
__device__ float g_kb[BATCH * NR];       // folded+scaled bias
__device__ float g_Wv[BATCH * NR * C];   // folded V         [b][j][c]

// ------------------------- f32x2 packed helpers ----------------------------
__device__ __forceinline__ unsigned long long pack2(float lo, float hi) {
    unsigned long long r;
    asm("mov.b64 %0, {%1, %2};" : "=l"(r) : "f"(lo), "f"(hi));
    return r;
}
__device__ __forceinline__ void unpack2(unsigned long long v, float& lo, float& hi) {
    asm("mov.b64 {%0, %1}, %2;" : "=f"(lo), "=f"(hi) : "l"(v));
}
__device__ __forceinline__ unsigned long long fma2(unsigned long long a,
                                                   unsigned long long b,
                                                   unsigned long long c) {
    unsigned long long d;
    asm("fma.rn.f32x2 %0, %1, %2, %3;" : "=l"(d) : "l"(a), "l"(b), "l"(c));
    return d;
}

// ---------------------------------------------------------------------------
// Kernel 1: transpose conv weights OIHW -> [kh][kw][ic][oc].
// ---------------------------------------------------------------------------
__global__ void prep_w_kernel(const float* __restrict__ sr_w) {
    int i = blockIdx.x * blockDim.x + threadIdx.x;
    int oc = i & 63;
    int ic = (i >> 6) & 63;
    int kw = (i >> 12) & 7;
    int kh = (i >> 15) & 7;
    g_wT[i] = sr_w[((oc * 64 + ic) * 8 + kh) * 8 + kw];
}

// ---------------------------------------------------------------------------
// Kernel 2: 8x8 stride-8 conv + bias. Grid (16, 8), 256 threads.
// ---------------------------------------------------------------------------
__global__ void conv_kernel(const float* __restrict__ x,
                            const float* __restrict__ sr_b) {
    __shared__ float xs[8192];
    __shared__ float ws[4096];

    const int oh = blockIdx.x;
    const int b  = blockIdx.y;
    const int t  = threadIdx.x;
    const int ow = t >> 4;
    const int g  = t & 15;

    float a0 = 0.f, a1 = 0.f, a2 = 0.f, a3 = 0.f;

    for (int kh = 0; kh < 8; kh++) {
        __syncthreads();
        const float4* src =
            (const float4*)(x + ((size_t)(b * NQ + (oh * 8 + kh) * 128)) * C);
        float4* xs4 = (float4*)xs;
        #pragma unroll
        for (int i = t; i < 2048; i += 256) xs4[i] = src[i];

        for (int kw = 0; kw < 8; kw++) {
            __syncthreads();
            const float4* wsrc = (const float4*)(g_wT + (kh * 8 + kw) * 4096);
            float4* ws4 = (float4*)ws;
            #pragma unroll
            for (int i = t; i < 1024; i += 256) ws4[i] = wsrc[i];
            __syncthreads();

            const float* xp = xs + (ow * 8 + kw) * 64;
            const float4* wp = (const float4*)ws + g;
            #pragma unroll 8
            for (int ic = 0; ic < 64; ic++) {
                float xv = xp[ic];
                float4 w4 = wp[ic * 16];
                a0 = fmaf(xv, w4.x, a0);
                a1 = fmaf(xv, w4.y, a1);
                a2 = fmaf(xv, w4.z, a2);
                a3 = fmaf(xv, w4.w, a3);
            }
        }
    }

    int oc = 4 * g;
    float4 o;
    o.x = a0 + sr_b[oc + 0];
    o.y = a1 + sr_b[oc + 1];
    o.z = a2 + sr_b[oc + 2];
    o.w = a3 + sr_b[oc + 3];
    size_t row = (size_t)b * NR + oh * 16 + ow;
    ((float4*)(g_xr + row * C))[g] = o;
}

// ---------------------------------------------------------------------------
// Kernel 3: LN + KV proj + fold. Writes g_Kt, g_kb, g_Wv.
// ---------------------------------------------------------------------------
__global__ void ln_fold_kernel(const float* __restrict__ ln_g,
                               const float* __restrict__ ln_b,
                               const float* __restrict__ q_w,
                               const float* __restrict__ q_b,
                               const float* __restrict__ kv_w,
                               const float* __restrict__ kv_b,
                               const float* __restrict__ proj_w) {
    __shared__ float sy[64], sk[64], sv[64], red[4];
    const int t = threadIdx.x;

    for (int rr = 0; rr < 8; rr++) {
        int row = blockIdx.x * 8 + rr;  // 0..2047
        float v = g_xr[row * 64 + t];

        float s = v, sq = v * v;
        #pragma unroll
        for (int off = 16; off > 0; off >>= 1) {
            s  += __shfl_xor_sync(0xffffffffu, s, off);
            sq += __shfl_xor_sync(0xffffffffu, sq, off);
        }
        if ((t & 31) == 0) { red[t >> 5] = s; red[2 + (t >> 5)] = sq; }
        __syncthreads();
        float mu  = (red[0] + red[1]) * (1.0f / 64.0f);
        float var = (red[2] + red[3]) * (1.0f / 64.0f) - mu * mu;
        float y   = (v - mu) * rsqrtf(var + 1e-5f) * ln_g[t] + ln_b[t];
        sy[t] = y;
        __syncthreads();

        float kd = kv_b[t], vd = kv_b[64 + t];
        const float* kwk = kv_w + t * 64;
        const float* kwv = kv_w + (64 + t) * 64;
        #pragma unroll 8
        for (int c = 0; c < 64; c++) {
            kd = fmaf(sy[c], kwk[c], kd);
            vd = fmaf(sy[c], kwv[c], vd);
        }
        sk[t] = kd; sv[t] = vd;
        __syncthreads();

        float kt = 0.f, wv = 0.f;
        const float* pw = proj_w + t * 64;
        #pragma unroll 8
        for (int d = 0; d < 64; d++) {
            kt = fmaf(sk[d], q_w[d * 64 + t], kt);
            wv = fmaf(sv[d], pw[d], wv);
        }
        g_Kt[row * 64 + t] = kt * SCALEF;
        g_Wv[row * 64 + t] = wv;
        if (t == 0) {
            float kb = 0.f;
            for (int d = 0; d < 64; d++) kb = fmaf(q_b[d], sk[d], kb);
            g_kb[row] = kb * SCALEF;
        }
        __syncthreads();
    }
}

// ---------------------------------------------------------------------------
// Kernel 4: cooperative attention, j-chunked for occupancy.
// CTA = 64 query rows, 128 threads, grid (256, 8); 3 CTAs/SM.
// Thread: jg = t&7, rg = t>>3; owns rows {rg+16i, i<4}.
//   pass1: j = 32h + 8p + jg (two halves h to bound regs)
//   pass2: channels {8jg .. 8jg+7}
// Smem floats: sX 64*68 | sKc 64*68 | sWc 64*68 | sP 64*68 | kb 256 | pb 64
// ---------------------------------------------------------------------------
#define ATTN_SMEM_FLOATS (4 * 4352 + 256 + 64)
#define ATTN_SMEM_BYTES  (ATTN_SMEM_FLOATS * 4)

__global__ __launch_bounds__(128, 3)
void attn_kernel(const float* __restrict__ x,
                 const float* __restrict__ proj_b,
                 float* __restrict__ out) {
    extern __shared__ float sm[];
    float* sX  = sm;              // 64*68
    float* sKc = sm + 4352;       // 64*68  current Kt chunk
    float* sWc = sm + 8704;       // 64*68  current Wv chunk
    float* sP  = sm + 13056;      // 64*68
    float* skb = sm + 17408;      // 256
    float* spb = sm + 17664;      // 64

    const int t    = threadIdx.x;
    const int tile = blockIdx.x;  // 0..255
    const int b    = blockIdx.y;  // 0..7

    // ---- stage X tile + kb (ALL 256 entries) + pb ----
    {
        const float4* gx =
            (const float4*)(x + ((size_t)b * NQ + (size_t)tile * 64) * C);
        #pragma unroll
        for (int i = 0; i < 8; i++) {
            int e = t + i * 128;                 // 0..1023
            float4 v = gx[e];
            *(float4*)&sX[(e >> 4) * RS + (e & 15) * 4] = v;
        }
        skb[t]       = g_kb[b * NR + t];
        skb[t + 128] = g_kb[b * NR + t + 128];   // second half (128 threads!)
        if (t < 64) spb[t] = proj_b[t];
    }
    __syncthreads();

    const int jg = t & 7;
    const int rg = t >> 3;

    unsigned long long acc2[4][4];
    #pragma unroll
    for (int i = 0; i < 4; i++)
        #pragma unroll
        for (int q = 0; q < 4; q++) acc2[i][q] = 0ull;
    float dsum[4] = {0.f, 0.f, 0.f, 0.f};

    const float4* gkB = (const float4*)(g_Kt + (size_t)b * NR * C);
    const float4* gwB = (const float4*)(g_Wv + (size_t)b * NR * C);

    #pragma unroll 1
    for (int c = 0; c < 4; c++) {
        // ---- stage Kt / Wv chunk (64 j-rows each) ----
        #pragma unroll
        for (int i = 0; i < 8; i++) {
            int e = t + i * 128;                 // 0..1023
            float4 kv = gkB[c * 1024 + e];
            *(float4*)&sKc[(e >> 4) * RS + (e & 15) * 4] = kv;
            float4 wv = gwB[c * 1024 + e];
            *(float4*)&sWc[(e >> 4) * RS + (e & 15) * 4] = wv;
        }
        __syncthreads();

        // ===== pass 1: S = X @ Kc^T, exp -> sP (two 32-j halves) =====
        #pragma unroll 1
        for (int h = 0; h < 2; h++) {
            unsigned long long s2[4][4];
            #pragma unroll
            for (int i = 0; i < 4; i++)
                #pragma unroll
                for (int p = 0; p < 4; p++) s2[i][p] = 0ull;

            #pragma unroll 4
            for (int k = 0; k < 64; k += 4) {
                unsigned long long xlo[4], xhi[4];
                #pragma unroll
                for (int i = 0; i < 4; i++) {
                    float4 v = *(const float4*)&sX[(rg + 16 * i) * RS + k];
                    xlo[i] = pack2(v.x, v.y);
                    xhi[i] = pack2(v.z, v.w);
                }
                #pragma unroll
                for (int p = 0; p < 4; p++) {
                    float4 kv =
                        *(const float4*)&sKc[(32 * h + 8 * p + jg) * RS + k];
                    unsigned long long klo = pack2(kv.x, kv.y);
                    unsigned long long khi = pack2(kv.z, kv.w);
                    #pragma unroll
                    for (int i = 0; i < 4; i++) {
                        s2[i][p] = fma2(xlo[i], klo, s2[i][p]);
                        s2[i][p] = fma2(xhi[i], khi, s2[i][p]);
                    }
                }
            }
            const float* kbp = skb + c * 64 + 32 * h;
            #pragma unroll
            for (int p = 0; p < 4; p++) {
                float kbv = kbp[8 * p + jg];
                #pragma unroll
                for (int i = 0; i < 4; i++) {
                    float a, bb;
                    unpack2(s2[i][p], a, bb);
                    float e = __expf(a + bb + kbv);
                    dsum[i] += e;
                    sP[(rg + 16 * i) * RS + 32 * h + 8 * p + jg] = e;
                }
            }
        }
        __syncthreads();  // sP fully produced block-wide before pass 2

        // ===== pass 2: acc += P @ Wc =====
        #pragma unroll 2
        for (int jj = 0; jj < 64; jj += 2) {
            const float* w0 = &sWc[jj * RS + jg * 8];
            const float* w1 = w0 + RS;
            float4 wa0 = *(const float4*)w0;
            float4 wb0 = *(const float4*)(w0 + 4);
            float4 wa1 = *(const float4*)w1;
            float4 wb1 = *(const float4*)(w1 + 4);
            unsigned long long w0q0 = pack2(wa0.x, wa0.y);
            unsigned long long w0q1 = pack2(wa0.z, wa0.w);
            unsigned long long w0q2 = pack2(wb0.x, wb0.y);
            unsigned long long w0q3 = pack2(wb0.z, wb0.w);
            unsigned long long w1q0 = pack2(wa1.x, wa1.y);
            unsigned long long w1q1 = pack2(wa1.z, wa1.w);
            unsigned long long w1q2 = pack2(wb1.x, wb1.y);
            unsigned long long w1q3 = pack2(wb1.z, wb1.w);
            #pragma unroll
            for (int i = 0; i < 4; i++) {
                float2 pv = *(const float2*)&sP[(rg + 16 * i) * RS + jj];
                unsigned long long p0 = pack2(pv.x, pv.x);
                unsigned long long p1 = pack2(pv.y, pv.y);
                acc2[i][0] = fma2(p0, w0q0, acc2[i][0]);
                acc2[i][1] = fma2(p0, w0q1, acc2[i][1]);
                acc2[i][2] = fma2(p0, w0q2, acc2[i][2]);
                acc2[i][3] = fma2(p0, w0q3, acc2[i][3]);
                acc2[i][0] = fma2(p1, w1q0, acc2[i][0]);
                acc2[i][1] = fma2(p1, w1q1, acc2[i][1]);
                acc2[i][2] = fma2(p1, w1q2, acc2[i][2]);
                acc2[i][3] = fma2(p1, w1q3, acc2[i][3]);
            }
        }
        __syncthreads();  // Kc/Wc/sP reused next chunk
    }

    // ---- den: reduce across the 8 j-groups (lanes sharing rg) ----
    #pragma unroll
    for (int i = 0; i < 4; i++) {
        #pragma unroll
        for (int off = 1; off < 8; off <<= 1)
            dsum[i] += __shfl_xor_sync(0xffffffffu, dsum[i], off);
    }

    // ---- epilogue: out = acc/den + proj_b ----
    #pragma unroll
    for (int i = 0; i < 4; i++) {
        float inv = 1.0f / dsum[i];
        float o0, o1, o2, o3, o4, o5, o6, o7;
        unpack2(acc2[i][0], o0, o1);
        unpack2(acc2[i][1], o2, o3);
        unpack2(acc2[i][2], o4, o5);
        unpack2(acc2[i][3], o6, o7);
        const float* pb = spb + jg * 8;
        float4* orow = (float4*)(out +
            ((size_t)b * NQ + (size_t)tile * 64 + rg + 16 * i) * C + jg * 8);
        float4 r0, r1;
        r0.x = fmaf(o0, inv, pb[0]);
        r0.y = fmaf(o1, inv, pb[1]);
        r0.z = fmaf(o2, inv, pb[2]);
        r0.w = fmaf(o3, inv, pb[3]);
        r1.x = fmaf(o4, inv, pb[4]);
        r1.y = fmaf(o5, inv, pb[5]);
        r1.z = fmaf(o6, inv, pb[6]);
        r1.w = fmaf(o7, inv, pb[7]);
        orow[0] = r0;
        orow[1] = r1;
    }
}

// ---------------------------------------------------------------------------
extern "C" void kernel_launch(void* const* d_in, const int* in_sizes, int n_in,
                              void* d_out, int out_size) {
    const float* x      = (const float*)d_in[0];
    const float* sr_w   = (const float*)d_in[1];
    const float* sr_b   = (const float*)d_in[2];
    const float* ln_g   = (const float*)d_in[3];
    const float* ln_b   = (const float*)d_in[4];
    const float* q_w    = (const float*)d_in[5];
    const float* q_b    = (const float*)d_in[6];
    const float* kv_w   = (const float*)d_in[7];
    const float* kv_b   = (const float*)d_in[8];
    const float* proj_w = (const float*)d_in[9];
    const float* proj_b = (const float*)d_in[10];
    float* out = (float*)d_out;

    static bool attr_set = false;
    if (!attr_set) {
        cudaFuncSetAttribute(attn_kernel,
                             cudaFuncAttributeMaxDynamicSharedMemorySize,
                             ATTN_SMEM_BYTES);
        attr_set = true;
    }

    prep_w_kernel<<<256, 1024>>>(sr_w);
    conv_kernel<<<dim3(16, 8), 256>>>(x, sr_b);
    ln_fold_kernel<<<256, 64>>>(ln_g, ln_b, q_w, q_b, kv_w, kv_b, proj_w);
    attn_kernel<<<dim3(256, 8), 128, ATTN_SMEM_BYTES>>>(x, proj_b, out);
}

// round 13
// speedup vs baseline: 1.6464x; 1.0483x over previous
#include <cuda_runtime.h>
#include <cstdint>

// ---------------------------------------------------------------------------
// EfficientSelfAttention (PVT spatial-reduction attention), fp32.
//   B=8, N=16384 (128x128), C=64, heads=1, SR=8 -> Nr=256.
//
//   xr   = conv8x8s8(x) + sr_b ; y = LN(xr)
//   Kt   = (K @ q_w) * SCALE ; kb = (K @ q_b) * SCALE   (fold q-proj)
//   Wv   = V @ proj_w.T                                 (fold out-proj)
//   s_nj = x_n . Kt_j + kb_j ; p = exp(s), den = row-sum
//   out  = (p @ Wv)/den + proj_b
//
// Attention: 64-row CTA / 128 threads / 2 j-chunks of 128.
// 8x8 register tiles in both passes (~1.0 smem bytes/MAC), XOR bank swizzles,
// P aliases the Kt smem buffer, 2 CTAs/SM.
// ---------------------------------------------------------------------------

#define BATCH 8
#define NQ    16384
#define C     64
#define NR    256
#define SCALEF 0.125f

__device__ float g_wT[64 * 64 * 64];     // conv weights [kh*8+kw][ic][oc]
__device__ float g_xr[BATCH * NR * C];   // conv output (pre-LN)
__device__ float g_KtT[BATCH * C * NR];  // folded+scaled K, TRANSPOSED [b][c][j]
__device__ float g_kb[BATCH * NR];       // folded+scaled bias
__device__ float g_Wv[BATCH * NR * C];   // folded V [b][j][c]

typedef unsigned long long u64;

__device__ __forceinline__ u64 pack2(float lo, float hi) {
    u64 r;
    asm("mov.b64 %0, {%1, %2};" : "=l"(r) : "f"(lo), "f"(hi));
    return r;
}
__device__ __forceinline__ void unpack2(u64 v, float& lo, float& hi) {
    asm("mov.b64 {%0, %1}, %2;" : "=f"(lo), "=f"(hi) : "l"(v));
}
__device__ __forceinline__ u64 fma2(u64 a, u64 b, u64 c) {
    u64 d;
    asm("fma.rn.f32x2 %0, %1, %2, %3;" : "=l"(d) : "l"(a), "l"(b), "l"(c));
    return d;
}

// ---------------------------------------------------------------------------
// Kernel 1: transpose conv weights OIHW -> [kh][kw][ic][oc].
// ---------------------------------------------------------------------------
__global__ void prep_w_kernel(const float* __restrict__ sr_w) {
    int i = blockIdx.x * blockDim.x + threadIdx.x;
    int oc = i & 63;
    int ic = (i >> 6) & 63;
    int kw = (i >> 12) & 7;
    int kh = (i >> 15) & 7;
    g_wT[i] = sr_w[((oc * 64 + ic) * 8 + kh) * 8 + kw];
}

// ---------------------------------------------------------------------------
// Kernel 2: 8x8 stride-8 conv + bias. Grid (16, 8), 256 threads.
// ---------------------------------------------------------------------------
__global__ void conv_kernel(const float* __restrict__ x,
                            const float* __restrict__ sr_b) {
    __shared__ float xs[8192];
    __shared__ float ws[4096];

    const int oh = blockIdx.x;
    const int b  = blockIdx.y;
    const int t  = threadIdx.x;
    const int ow = t >> 4;
    const int g  = t & 15;

    float a0 = 0.f, a1 = 0.f, a2 = 0.f, a3 = 0.f;

    for (int kh = 0; kh < 8; kh++) {
        __syncthreads();
        const float4* src =
            (const float4*)(x + ((size_t)(b * NQ + (oh * 8 + kh) * 128)) * C);
        float4* xs4 = (float4*)xs;
        #pragma unroll
        for (int i = t; i < 2048; i += 256) xs4[i] = src[i];

        for (int kw = 0; kw < 8; kw++) {
            __syncthreads();
            const float4* wsrc = (const float4*)(g_wT + (kh * 8 + kw) * 4096);
            float4* ws4 = (float4*)ws;
            #pragma unroll
            for (int i = t; i < 1024; i += 256) ws4[i] = wsrc[i];
            __syncthreads();

            const float* xp = xs + (ow * 8 + kw) * 64;
            const float4* wp = (const float4*)ws + g;
            #pragma unroll 8
            for (int ic = 0; ic < 64; ic++) {
                float xv = xp[ic];
                float4 w4 = wp[ic * 16];
                a0 = fmaf(xv, w4.x, a0);
                a1 = fmaf(xv, w4.y, a1);
                a2 = fmaf(xv, w4.z, a2);
                a3 = fmaf(xv, w4.w, a3);
            }
        }
    }

    int oc = 4 * g;
    float4 o;
    o.x = a0 + sr_b[oc + 0];
    o.y = a1 + sr_b[oc + 1];
    o.z = a2 + sr_b[oc + 2];
    o.w = a3 + sr_b[oc + 3];
    size_t row = (size_t)b * NR + oh * 16 + ow;
    ((float4*)(g_xr + row * C))[g] = o;
}

// ---------------------------------------------------------------------------
// Kernel 3: LN + KV proj + fold. Writes g_KtT (transposed), g_kb, g_Wv.
// ---------------------------------------------------------------------------
__global__ void ln_fold_kernel(const float* __restrict__ ln_g,
                               const float* __restrict__ ln_b,
                               const float* __restrict__ q_w,
                               const float* __restrict__ q_b,
                               const float* __restrict__ kv_w,
                               const float* __restrict__ kv_b,
                               const float* __restrict__ proj_w) {
    __shared__ float sy[64], sk[64], sv[64], red[4];
    const int t = threadIdx.x;

    for (int rr = 0; rr < 8; rr++) {
        int row = blockIdx.x * 8 + rr;  // 0..2047
        float v = g_xr[row * 64 + t];

        float s = v, sq = v * v;
        #pragma unroll
        for (int off = 16; off > 0; off >>= 1) {
            s  += __shfl_xor_sync(0xffffffffu, s, off);
            sq += __shfl_xor_sync(0xffffffffu, sq, off);
        }
        if ((t & 31) == 0) { red[t >> 5] = s; red[2 + (t >> 5)] = sq; }
        __syncthreads();
        float mu  = (red[0] + red[1]) * (1.0f / 64.0f);
        float var = (red[2] + red[3]) * (1.0f / 64.0f) - mu * mu;
        float y   = (v - mu) * rsqrtf(var + 1e-5f) * ln_g[t] + ln_b[t];
        sy[t] = y;
        __syncthreads();

        float kd = kv_b[t], vd = kv_b[64 + t];
        const float* kwk = kv_w + t * 64;
        const float* kwv = kv_w + (64 + t) * 64;
        #pragma unroll 8
        for (int c = 0; c < 64; c++) {
            kd = fmaf(sy[c], kwk[c], kd);
            vd = fmaf(sy[c], kwv[c], vd);
        }
        sk[t] = kd; sv[t] = vd;
        __syncthreads();

        float kt = 0.f, wv = 0.f;
        const float* pw = proj_w + t * 64;
        #pragma unroll 8
        for (int d = 0; d < 64; d++) {
            kt = fmaf(sk[d], q_w[d * 64 + t], kt);
            wv = fmaf(sv[d], pw[d], wv);
        }
        // transposed: [b][channel t][j]
        g_KtT[(row >> 8) * (64 * 256) + t * 256 + (row & 255)] = kt * SCALEF;
        g_Wv[row * 64 + t] = wv;
        if (t == 0) {
            float kb = 0.f;
            for (int d = 0; d < 64; d++) kb = fmaf(q_b[d], sk[d], kb);
            g_kb[row] = kb * SCALEF;
        }
        __syncthreads();
    }
}

// ---------------------------------------------------------------------------
// Kernel 4: attention, 8x8 register tiles. CTA 64 rows, 128 thr, grid (256,8).
// pass1 map: rg=t>>4 (rows rg*8..+7), jg=t&15 (j = jg*8..+7, j-packed acc)
// pass2 map: rg=t>>4, cg=(t>>1)&7 (ch cg*8..+7), jh=t&1 (j-half), shfl merge
// smem: sX[64*68] | sKtT[64*132] (aliased by sP[64*132]) | sWc[128*68] |
//       den[64] kb[256] pb[64]
// ---------------------------------------------------------------------------
#define SM_X   0
#define SM_KT  4352
#define SM_WC  12800
#define SM_DEN 21504
#define SM_KB  21568
#define SM_PB  21824
#define ATTN_SMEM_FLOATS 21888
#define ATTN_SMEM_BYTES  (ATTN_SMEM_FLOATS * 4)

__global__ __launch_bounds__(128, 2)
void attn_kernel(const float* __restrict__ x,
                 const float* __restrict__ proj_b,
                 float* __restrict__ out) {
    extern __shared__ float sm[];
    float* sX   = sm + SM_X;    // [row][68]; k-quad kq at kq^(row>>3)
    float* sKtT = sm + SM_KT;   // [k][132]; j-block jb at jb^(jb>>3)
    float* sPB  = sm + SM_KT;   // P alias: [row][132]; block pp (see below)
    float* sWc  = sm + SM_WC;   // [j][68]; ch-block cb at cb^(cb>>3)
    float* sden = sm + SM_DEN;
    float* skb  = sm + SM_KB;
    float* spb  = sm + SM_PB;

    const int t    = threadIdx.x;
    const int tile = blockIdx.x;  // 0..255
    const int b    = blockIdx.y;  // 0..7

    const int rg = t >> 4;        // 0..7 row group (both passes)
    const int jg = t & 15;        // pass1 j group
    const int cg = (t >> 1) & 7;  // pass2 channel group
    const int jh = t & 1;         // pass2 j half

    // ---- stage X (swizzled) + kb (all 256) + pb ----
    {
        const float4* gx =
            (const float4*)(x + ((size_t)b * NQ + (size_t)tile * 64) * C);
        #pragma unroll
        for (int n = 0; n < 8; n++) {
            int e = t + n * 128;             // 0..1023
            int row = e >> 4, kq = e & 15;
            float4 v = gx[e];
            *(float4*)&sX[row * 68 + ((kq ^ (row >> 3)) << 2)] = v;
        }
        skb[t]       = g_kb[b * NR + t];
        skb[t + 128] = g_kb[b * NR + t + 128];
        if (t < 64) spb[t] = proj_b[t];
    }

    const int jb0 = jg * 2,     qb0 = jb0 ^ (jb0 >> 3);
    const int jb1 = jg * 2 + 1, qb1 = jb1 ^ (jb1 >> 3);
    const int cb0 = cg * 2,     qc0 = cb0 ^ (cb0 >> 3);
    const int cb1 = cg * 2 + 1, qc1 = cb1 ^ (cb1 >> 3);

    u64 o2[8][4];
    #pragma unroll
    for (int i = 0; i < 8; i++)
        #pragma unroll
        for (int q = 0; q < 4; q++) o2[i][q] = 0ull;
    float dsum[8];
    #pragma unroll
    for (int i = 0; i < 8; i++) dsum[i] = 0.f;

    const float* gktB = g_KtT + (size_t)b * C * NR;
    const float* gwB  = g_Wv + (size_t)b * NR * C;

    #pragma unroll 1
    for (int c = 0; c < 2; c++) {
        // ---- stage Kt chunk [64k][128j] and Wv chunk [128j][64ch] ----
        #pragma unroll
        for (int n = 0; n < 16; n++) {
            int e = t + n * 128;             // 0..2047 float4s
            int k  = e >> 5, jbs = e & 31;
            float4 kv = *(const float4*)(gktB + k * 256 + c * 128 + jbs * 4);
            *(float4*)&sKtT[k * 132 + ((jbs ^ (jbs >> 3)) << 2)] = kv;
            int j  = e >> 4, cbs = e & 15;
            float4 wv =
                *(const float4*)(gwB + ((size_t)c * 128 + j) * 64 + cbs * 4);
            *(float4*)&sWc[j * 68 + ((cbs ^ (cbs >> 3)) << 2)] = wv;
        }
        __syncthreads();

        // ===== pass 1: S[8r][8j] = X @ Kt^T (j-packed accumulators) =====
        u64 s2[8][4];
        #pragma unroll
        for (int i = 0; i < 8; i++)
            #pragma unroll
            for (int q = 0; q < 4; q++) s2[i][q] = 0ull;

        #pragma unroll 2
        for (int kq = 0; kq < 16; kq++) {
            float4 xq[8];
            #pragma unroll
            for (int i = 0; i < 8; i++)
                xq[i] =
                    *(const float4*)&sX[(rg * 8 + i) * 68 + ((kq ^ rg) << 2)];
            #pragma unroll
            for (int kk = 0; kk < 4; kk++) {
                int k = kq * 4 + kk;
                ulonglong2 k01 = *(const ulonglong2*)&sKtT[k * 132 + (qb0 << 2)];
                ulonglong2 k23 = *(const ulonglong2*)&sKtT[k * 132 + (qb1 << 2)];
                #pragma unroll
                for (int i = 0; i < 8; i++) {
                    float xv = ((const float*)&xq[i])[kk];
                    u64 xp = pack2(xv, xv);
                    s2[i][0] = fma2(xp, k01.x, s2[i][0]);
                    s2[i][1] = fma2(xp, k01.y, s2[i][1]);
                    s2[i][2] = fma2(xp, k23.x, s2[i][2]);
                    s2[i][3] = fma2(xp, k23.y, s2[i][3]);
                }
            }
        }
        __syncthreads();  // all Kt reads done (sPB aliases sKtT)

        // ---- exp + kb, accumulate den, store P (swizzled) ----
        #pragma unroll
        for (int mp = 0; mp < 4; mp++) {
            int jl  = jg * 8 + 2 * mp;                // chunk-local j
            float kb0 = skb[c * 128 + jl];
            float kb1 = skb[c * 128 + jl + 1];
            int jbp = jl >> 2;                        // 4-float block index
            int wof = (jl & 3);                       // 0 or 2
            #pragma unroll
            for (int i = 0; i < 8; i++) {
                float sa, sb;
                unpack2(s2[i][mp], sa, sb);
                float e0 = __expf(sa + kb0);
                float e1 = __expf(sb + kb1);
                dsum[i] += e0 + e1;
                int row = rg * 8 + i;
                int pp = jbp ^ rg ^ (((jbp >> 4) & 1) << 2);
                *(u64*)&sPB[row * 132 + (pp << 2) + wof] = pack2(e0, e1);
            }
        }
        __syncthreads();  // P complete

        // ===== pass 2: o2[8r][8ch] += P[:, jh-half] @ Wv =====
        #pragma unroll 2
        for (int jq = 0; jq < 16; jq++) {
            int jl = jh * 64 + jq * 4;                // chunk-local j base
            int jbp = jl >> 2;
            int pp  = jbp ^ rg ^ (((jbp >> 4) & 1) << 2);
            float4 p4[8];
            #pragma unroll
            for (int i = 0; i < 8; i++)
                p4[i] = *(const float4*)&sPB[(rg * 8 + i) * 132 + (pp << 2)];
            #pragma unroll
            for (int jj = 0; jj < 4; jj++) {
                int j = jl + jj;
                ulonglong2 w01 = *(const ulonglong2*)&sWc[j * 68 + (qc0 << 2)];
                ulonglong2 w23 = *(const ulonglong2*)&sWc[j * 68 + (qc1 << 2)];
                #pragma unroll
                for (int i = 0; i < 8; i++) {
                    float pv = ((const float*)&p4[i])[jj];
                    u64 pk = pack2(pv, pv);
                    o2[i][0] = fma2(pk, w01.x, o2[i][0]);
                    o2[i][1] = fma2(pk, w01.y, o2[i][1]);
                    o2[i][2] = fma2(pk, w23.x, o2[i][2]);
                    o2[i][3] = fma2(pk, w23.y, o2[i][3]);
                }
            }
        }
        __syncthreads();  // sPB(KtT)/sWc reused next chunk
    }

    // ---- den: reduce across the 16 jg lanes, publish to smem ----
    #pragma unroll
    for (int i = 0; i < 8; i++) {
        #pragma unroll
        for (int off = 1; off < 16; off <<= 1)
            dsum[i] += __shfl_xor_sync(0xffffffffu, dsum[i], off);
    }
    if (jg == 0) {
        #pragma unroll
        for (int i = 0; i < 8; i++) sden[rg * 8 + i] = dsum[i];
    }
    __syncthreads();

    // ---- merge jh partials (lane pair t^1), float-wise ----
    #pragma unroll
    for (int i = 0; i < 8; i++) {
        #pragma unroll
        for (int q = 0; q < 4; q++) {
            u64 other = __shfl_xor_sync(0xffffffffu, o2[i][q], 1);
            float a0, a1, b0, b1;
            unpack2(o2[i][q], a0, a1);
            unpack2(other, b0, b1);
            o2[i][q] = pack2(a0 + b0, a1 + b1);
        }
    }

    // ---- epilogue: out = o2/den + proj_b (each jh writes 4 of the 8 rows) --
    #pragma unroll
    for (int i2 = 0; i2 < 4; i2++) {
        int i = jh * 4 + i2;
        int row = rg * 8 + i;
        float inv = 1.0f / sden[row];
        float e0, e1, e2, e3, e4, e5, e6, e7;
        unpack2(o2[i][0], e0, e1);
        unpack2(o2[i][1], e2, e3);
        unpack2(o2[i][2], e4, e5);
        unpack2(o2[i][3], e6, e7);
        const float* pb = spb + cg * 8;
        float4* orow = (float4*)(out +
            ((size_t)b * NQ + (size_t)tile * 64 + row) * C + cg * 8);
        float4 r0, r1;
        r0.x = fmaf(e0, inv, pb[0]);
        r0.y = fmaf(e1, inv, pb[1]);
        r0.z = fmaf(e2, inv, pb[2]);
        r0.w = fmaf(e3, inv, pb[3]);
        r1.x = fmaf(e4, inv, pb[4]);
        r1.y = fmaf(e5, inv, pb[5]);
        r1.z = fmaf(e6, inv, pb[6]);
        r1.w = fmaf(e7, inv, pb[7]);
        orow[0] = r0;
        orow[1] = r1;
    }
}

// ---------------------------------------------------------------------------
extern "C" void kernel_launch(void* const* d_in, const int* in_sizes, int n_in,
                              void* d_out, int out_size) {
    const float* x      = (const float*)d_in[0];
    const float* sr_w   = (const float*)d_in[1];
    const float* sr_b   = (const float*)d_in[2];
    const float* ln_g   = (const float*)d_in[3];
    const float* ln_b   = (const float*)d_in[4];
    const float* q_w    = (const float*)d_in[5];
    const float* q_b    = (const float*)d_in[6];
    const float* kv_w   = (const float*)d_in[7];
    const float* kv_b   = (const float*)d_in[8];
    const float* proj_w = (const float*)d_in[9];
    const float* proj_b = (const float*)d_in[10];
    float* out = (float*)d_out;

    static bool attr_set = false;
    if (!attr_set) {
        cudaFuncSetAttribute(attn_kernel,
                             cudaFuncAttributeMaxDynamicSharedMemorySize,
                             ATTN_SMEM_BYTES);
        attr_set = true;
    }

    prep_w_kernel<<<256, 1024>>>(sr_w);
    conv_kernel<<<dim3(16, 8), 256>>>(x, sr_b);
    ln_fold_kernel<<<256, 64>>>(ln_g, ln_b, q_w, q_b, kv_w, kv_b, proj_w);
    attn_kernel<<<dim3(256, 8), 128, ATTN_SMEM_BYTES>>>(x, proj_b, out);
}

// round 14
// speedup vs baseline: 2.2307x; 1.3549x over previous
#include <cuda_runtime.h>
#include <cstdint>

#define BATCH 8
#define NQ    16384
#define C     64
#define NR    256
#define SCALEF 0.125f

__device__ float g_wT[64 * 64 * 64];     // conv weights [kh*8+kw][ic][oc]
__device__ float g_kvT[64 * 128];        // kv_w transposed: [c][r] = kv_w[r][c]
__device__ float g_pwT[64 * 64];         // proj_w transposed: [d][t] = proj_w[t][d]
__device__ float g_xr[BATCH * NR * C];   // conv output (pre-LN)
__device__ float g_KtT[BATCH * C * NR];  // folded+scaled K, transposed [b][c][j]
__device__ float g_kb[BATCH * NR];       // folded+scaled bias
__device__ float g_Wv[BATCH * NR * C];   // folded V [b][j][c]

typedef unsigned long long u64;

__device__ __forceinline__ u64 pack2(float lo, float hi) {
    u64 r;
    asm("mov.b64 %0, {%1, %2};" : "=l"(r) : "f"(lo), "f"(hi));
    return r;
}
__device__ __forceinline__ void unpack2(u64 v, float& lo, float& hi) {
    asm("mov.b64 {%0, %1}, %2;" : "=f"(lo), "=f"(hi) : "l"(v));
}
__device__ __forceinline__ u64 fma2(u64 a, u64 b, u64 c) {
    u64 d;
    asm("fma.rn.f32x2 %0, %1, %2, %3;" : "=l"(d) : "l"(a), "l"(b), "l"(c));
    return d;
}

// ---------------------------------------------------------------------------
// Kernel 1: transpose conv weights OIHW -> [kh][kw][ic][oc].
// ---------------------------------------------------------------------------
__global__ void prep_w_kernel(const float* __restrict__ sr_w) {
    int i = blockIdx.x * blockDim.x + threadIdx.x;
    int oc = i & 63;
    int ic = (i >> 6) & 63;
    int kw = (i >> 12) & 7;
    int kh = (i >> 15) & 7;
    g_wT[i] = sr_w[((oc * 64 + ic) * 8 + kh) * 8 + kw];
}

// ---------------------------------------------------------------------------
// Kernel 1b: transpose kv_w (128x64 -> [c][r]) and proj_w (64x64 -> [d][t])
// so ln_fold weight reads are lane-coalesced.
// ---------------------------------------------------------------------------
__global__ void prep_t_kernel(const float* __restrict__ kv_w,
                              const float* __restrict__ proj_w) {
    int i = blockIdx.x * blockDim.x + threadIdx.x;  // 0..8191
    int c = i >> 7, r = i & 127;
    g_kvT[i] = kv_w[r * 64 + c];
    if (i < 4096) {
        int d = i >> 6, tt = i & 63;
        g_pwT[i] = proj_w[tt * 64 + d];
    }
}

// ---------------------------------------------------------------------------
// Kernel 2: 8x8 stride-8 conv + bias. Grid (16, 8), 256 threads.
// ---------------------------------------------------------------------------
__global__ void conv_kernel(const float* __restrict__ x,
                            const float* __restrict__ sr_b) {
    __shared__ float xs[8192];
    __shared__ float ws[4096];

    const int oh = blockIdx.x;
    const int b  = blockIdx.y;
    const int t  = threadIdx.x;
    const int ow = t >> 4;
    const int g  = t & 15;

    float a0 = 0.f, a1 = 0.f, a2 = 0.f, a3 = 0.f;

    for (int kh = 0; kh < 8; kh++) {
        __syncthreads();
        const float4* src =
            (const float4*)(x + ((size_t)(b * NQ + (oh * 8 + kh) * 128)) * C);
        float4* xs4 = (float4*)xs;
        #pragma unroll
        for (int i = t; i < 2048; i += 256) xs4[i] = src[i];

        for (int kw = 0; kw < 8; kw++) {
            __syncthreads();
            const float4* wsrc = (const float4*)(g_wT + (kh * 8 + kw) * 4096);
            float4* ws4 = (float4*)ws;
            #pragma unroll
            for (int i = t; i < 1024; i += 256) ws4[i] = wsrc[i];
            __syncthreads();

            const float* xp = xs + (ow * 8 + kw) * 64;
            const float4* wp = (const float4*)ws + g;
            #pragma unroll 8
            for (int ic = 0; ic < 64; ic++) {
                float xv = xp[ic];
                float4 w4 = wp[ic * 16];
                a0 = fmaf(xv, w4.x, a0);
                a1 = fmaf(xv, w4.y, a1);
                a2 = fmaf(xv, w4.z, a2);
                a3 = fmaf(xv, w4.w, a3);
            }
        }
    }

    int oc = 4 * g;
    float4 o;
    o.x = a0 + sr_b[oc + 0];
    o.y = a1 + sr_b[oc + 1];
    o.z = a2 + sr_b[oc + 2];
    o.w = a3 + sr_b[oc + 3];
    size_t row = (size_t)b * NR + oh * 16 + ow;
    ((float4*)(g_xr + row * C))[g] = o;
}

// ---------------------------------------------------------------------------
// Kernel 3: LN + KV proj + fold, with coalesced (transposed) weight reads.
// ---------------------------------------------------------------------------
__global__ void ln_fold_kernel(const float* __restrict__ ln_g,
                               const float* __restrict__ ln_b,
                               const float* __restrict__ q_w,
                               const float* __restrict__ q_b,
                               const float* __restrict__ kv_b) {
    __shared__ float sy[64], sk[64], sv[64], red[4];
    const int t = threadIdx.x;

    for (int rr = 0; rr < 8; rr++) {
        int row = blockIdx.x * 8 + rr;  // 0..2047
        float v = g_xr[row * 64 + t];

        float s = v, sq = v * v;
        #pragma unroll
        for (int off = 16; off > 0; off >>= 1) {
            s  += __shfl_xor_sync(0xffffffffu, s, off);
            sq += __shfl_xor_sync(0xffffffffu, sq, off);
        }
        if ((t & 31) == 0) { red[t >> 5] = s; red[2 + (t >> 5)] = sq; }
        __syncthreads();
        float mu  = (red[0] + red[1]) * (1.0f / 64.0f);
        float var = (red[2] + red[3]) * (1.0f / 64.0f) - mu * mu;
        float y   = (v - mu) * rsqrtf(var + 1e-5f) * ln_g[t] + ln_b[t];
        sy[t] = y;
        __syncthreads();

        float kd = kv_b[t], vd = kv_b[64 + t];
        #pragma unroll 8
        for (int c = 0; c < 64; c++) {
            kd = fmaf(sy[c], g_kvT[c * 128 + t], kd);
            vd = fmaf(sy[c], g_kvT[c * 128 + 64 + t], vd);
        }
        sk[t] = kd; sv[t] = vd;
        __syncthreads();

        float kt = 0.f, wv = 0.f;
        #pragma unroll 8
        for (int d = 0; d < 64; d++) {
            kt = fmaf(sk[d], q_w[d * 64 + t], kt);
            wv = fmaf(sv[d], g_pwT[d * 64 + t], wv);
        }
        g_KtT[(row >> 8) * (64 * 256) + t * 256 + (row & 255)] = kt * SCALEF;
        g_Wv[row * 64 + t] = wv;
        if (t == 0) {
            float kb = 0.f;
            for (int d = 0; d < 64; d++) kb = fmaf(q_b[d], sk[d], kb);
            g_kb[row] = kb * SCALEF;
        }
        __syncthreads();
    }
}

// ---------------------------------------------------------------------------
// Kernel 4: attention, register tiles sized to avoid spill.
// CTA 64 rows, 128 thr, grid (256,8), 2 j-chunks of 128, 2 CTAs/SM.
// pass1: rg=t>>4 rows rg*8..+7, jg=t&15 j jg*8..+7 (j-packed acc, 64 regs)
// pass2: rg=t>>4 rows,        cg2=t&15 ch cg2*4..+3 (o2 = 32 regs, full j)
// smem: sX[64*68] | sKtT[64*132] (aliased by sP) | sWc[128*68] |
//       den[64] kb[256] pb[64]
// ---------------------------------------------------------------------------
#define SM_X   0
#define SM_KT  4352
#define SM_WC  12800
#define SM_DEN 21504
#define SM_KB  21568
#define SM_PB  21824
#define ATTN_SMEM_FLOATS 21888
#define ATTN_SMEM_BYTES  (ATTN_SMEM_FLOATS * 4)

__global__ __launch_bounds__(128, 2)
void attn_kernel(const float* __restrict__ x,
                 const float* __restrict__ proj_b,
                 float* __restrict__ out) {
    extern __shared__ float sm[];
    float* sX   = sm + SM_X;    // [row][68]; k-quad kq at kq^(row>>3)
    float* sKtT = sm + SM_KT;   // [k][132]; j-block jb at jb^(jb>>3)
    float* sPB  = sm + SM_KT;   // P alias: [row][132]
    float* sWc  = sm + SM_WC;   // [j][68]; ch-block cb at cb^(cb>>3)
    float* sden = sm + SM_DEN;
    float* skb  = sm + SM_KB;
    float* spb  = sm + SM_PB;

    const int t    = threadIdx.x;
    const int tile = blockIdx.x;  // 0..255
    const int b    = blockIdx.y;  // 0..7

    const int rg  = t >> 4;       // 0..7 row group (both passes)
    const int jg  = t & 15;       // pass1 j group
    const int cg2 = t & 15;       // pass2 channel group (4 ch)

    // ---- stage X (swizzled) + kb (all 256) + pb ----
    {
        const float4* gx =
            (const float4*)(x + ((size_t)b * NQ + (size_t)tile * 64) * C);
        #pragma unroll
        for (int n = 0; n < 8; n++) {
            int e = t + n * 128;             // 0..1023
            int row = e >> 4, kq = e & 15;
            float4 v = gx[e];
            *(float4*)&sX[row * 68 + ((kq ^ (row >> 3)) << 2)] = v;
        }
        skb[t]       = g_kb[b * NR + t];
        skb[t + 128] = g_kb[b * NR + t + 128];
        if (t < 64) spb[t] = proj_b[t];
    }

    const int jb0 = jg * 2,      qb0 = jb0 ^ (jb0 >> 3);
    const int jb1 = jg * 2 + 1,  qb1 = jb1 ^ (jb1 >> 3);
    const int qc  = cg2 ^ (cg2 >> 3);

    u64 o2[8][2];
    #pragma unroll
    for (int i = 0; i < 8; i++) { o2[i][0] = 0ull; o2[i][1] = 0ull; }
    float dsum[8];
    #pragma unroll
    for (int i = 0; i < 8; i++) dsum[i] = 0.f;

    const float* gktB = g_KtT + (size_t)b * C * NR;
    const float* gwB  = g_Wv + (size_t)b * NR * C;

    #pragma unroll 1
    for (int c = 0; c < 2; c++) {
        // ---- stage Kt chunk [64k][128j] and Wv chunk [128j][64ch] ----
        #pragma unroll
        for (int n = 0; n < 16; n++) {
            int e = t + n * 128;             // 0..2047 float4s
            int k  = e >> 5, jbs = e & 31;
            float4 kv = *(const float4*)(gktB + k * 256 + c * 128 + jbs * 4);
            *(float4*)&sKtT[k * 132 + ((jbs ^ (jbs >> 3)) << 2)] = kv;
            int j  = e >> 4, cbs = e & 15;
            float4 wv =
                *(const float4*)(gwB + ((size_t)c * 128 + j) * 64 + cbs * 4);
            *(float4*)&sWc[j * 68 + ((cbs ^ (cbs >> 3)) << 2)] = wv;
        }
        __syncthreads();

        // ===== pass 1: S[8r][8j] = X @ Kt^T (j-packed accumulators) =====
        u64 s2[8][4];
        #pragma unroll
        for (int i = 0; i < 8; i++)
            #pragma unroll
            for (int q = 0; q < 4; q++) s2[i][q] = 0ull;

        #pragma unroll 1
        for (int kq = 0; kq < 16; kq++) {
            float4 xq[8];
            #pragma unroll
            for (int i = 0; i < 8; i++)
                xq[i] =
                    *(const float4*)&sX[(rg * 8 + i) * 68 + ((kq ^ rg) << 2)];
            #pragma unroll
            for (int kk = 0; kk < 4; kk++) {
                int k = kq * 4 + kk;
                ulonglong2 k01 = *(const ulonglong2*)&sKtT[k * 132 + (qb0 << 2)];
                ulonglong2 k23 = *(const ulonglong2*)&sKtT[k * 132 + (qb1 << 2)];
                #pragma unroll
                for (int i = 0; i < 8; i++) {
                    float xv = ((const float*)&xq[i])[kk];
                    u64 xp = pack2(xv, xv);
                    s2[i][0] = fma2(xp, k01.x, s2[i][0]);
                    s2[i][1] = fma2(xp, k01.y, s2[i][1]);
                    s2[i][2] = fma2(xp, k23.x, s2[i][2]);
                    s2[i][3] = fma2(xp, k23.y, s2[i][3]);
                }
            }
        }
        __syncthreads();  // all Kt reads done (sPB aliases sKtT)

        // ---- exp + kb, accumulate den, store P (swizzled) ----
        #pragma unroll
        for (int mp = 0; mp < 4; mp++) {
            int jl  = jg * 8 + 2 * mp;                // chunk-local j
            float kb0 = skb[c * 128 + jl];
            float kb1 = skb[c * 128 + jl + 1];
            int jbp = jl >> 2;
            int wof = (jl & 3);
            #pragma unroll
            for (int i = 0; i < 8; i++) {
                float sa, sb;
                unpack2(s2[i][mp], sa, sb);
                float e0 = __expf(sa + kb0);
                float e1 = __expf(sb + kb1);
                dsum[i] += e0 + e1;
                int row = rg * 8 + i;
                int pp = jbp ^ rg ^ (((jbp >> 4) & 1) << 2);
                *(u64*)&sPB[row * 132 + (pp << 2) + wof] = pack2(e0, e1);
            }
        }
        __syncthreads();  // P complete

        // ===== pass 2: o2[8r][4ch] += P @ Wv (full j range) =====
        #pragma unroll 1
        for (int jq = 0; jq < 32; jq++) {
            int pp = jq ^ rg ^ (((jq >> 4) & 1) << 2);
            float4 p4[8];
            #pragma unroll
            for (int i = 0; i < 8; i++)
                p4[i] = *(const float4*)&sPB[(rg * 8 + i) * 132 + (pp << 2)];
            #pragma unroll
            for (int jj = 0; jj < 4; jj++) {
                int j = jq * 4 + jj;
                ulonglong2 w2 = *(const ulonglong2*)&sWc[j * 68 + (qc << 2)];
                #pragma unroll
                for (int i = 0; i < 8; i++) {
                    float pv = ((const float*)&p4[i])[jj];
                    u64 pk = pack2(pv, pv);
                    o2[i][0] = fma2(pk, w2.x, o2[i][0]);
                    o2[i][1] = fma2(pk, w2.y, o2[i][1]);
                }
            }
        }
        __syncthreads();  // sPB(KtT)/sWc reused next chunk
    }

    // ---- den: reduce across the 16 jg lanes, publish to smem ----
    #pragma unroll
    for (int i = 0; i < 8; i++) {
        #pragma unroll
        for (int off = 1; off < 16; off <<= 1)
            dsum[i] += __shfl_xor_sync(0xffffffffu, dsum[i], off);
    }
    if (jg == 0) {
        #pragma unroll
        for (int i = 0; i < 8; i++) sden[rg * 8 + i] = dsum[i];
    }
    __syncthreads();

    // ---- epilogue: out = o2/den + proj_b (thread owns 8 rows x 4 ch) ----
    #pragma unroll
    for (int i = 0; i < 8; i++) {
        int row = rg * 8 + i;
        float inv = 1.0f / sden[row];
        float e0, e1, e2, e3;
        unpack2(o2[i][0], e0, e1);
        unpack2(o2[i][1], e2, e3);
        const float* pb = spb + cg2 * 4;
        float4 r0;
        r0.x = fmaf(e0, inv, pb[0]);
        r0.y = fmaf(e1, inv, pb[1]);
        r0.z = fmaf(e2, inv, pb[2]);
        r0.w = fmaf(e3, inv, pb[3]);
        *(float4*)(out +
            ((size_t)b * NQ + (size_t)tile * 64 + row) * C + cg2 * 4) = r0;
    }
}

// ---------------------------------------------------------------------------
extern "C" void kernel_launch(void* const* d_in, const int* in_sizes, int n_in,
                              void* d_out, int out_size) {
    const float* x      = (const float*)d_in[0];
    const float* sr_w   = (const float*)d_in[1];
    const float* sr_b   = (const float*)d_in[2];
    const float* ln_g   = (const float*)d_in[3];
    const float* ln_b   = (const float*)d_in[4];
    const float* q_w    = (const float*)d_in[5];
    const float* q_b    = (const float*)d_in[6];
    const float* kv_w   = (const float*)d_in[7];
    const float* kv_b   = (const float*)d_in[8];
    const float* proj_w = (const float*)d_in[9];
    const float* proj_b = (const float*)d_in[10];
    float* out = (float*)d_out;

    static bool attr_set = false;
    if (!attr_set) {
        cudaFuncSetAttribute(attn_kernel,
                             cudaFuncAttributeMaxDynamicSharedMemorySize,
                             ATTN_SMEM_BYTES);
        attr_set = true;
    }

    prep_w_kernel<<<256, 1024>>>(sr_w);
    prep_t_kernel<<<8, 1024>>>(kv_w, proj_w);
    conv_kernel<<<dim3(16, 8), 256>>>(x, sr_b);
    ln_fold_kernel<<<256, 64>>>(ln_g, ln_b, q_w, q_b, kv_b);
    attn_kernel<<<dim3(256, 8), 128, ATTN_SMEM_BYTES>>>(x, proj_b, out);
}

// round 15
// speedup vs baseline: 2.3688x; 1.0619x over previous
#include <cuda_runtime.h>
#include <cstdint>

#define BATCH 8
#define NQ    16384
#define C     64
#define NR    256
#define SCALEF 0.125f

__device__ float g_wT[64 * 64 * 64];     // conv weights [kh*8+kw][ic][oc]
__device__ float g_kvT[64 * 128];        // kv_w transposed: [c][r]
__device__ float g_pwT[64 * 64];         // proj_w transposed: [d][t]
__device__ float g_xr[BATCH * NR * C];   // conv output (pre-LN)
__device__ float g_KtT[BATCH * C * NR];  // folded+scaled K, transposed [b][c][j]
__device__ float g_kb[BATCH * NR];       // folded+scaled bias
__device__ float g_Wv[BATCH * NR * C];   // folded V [b][j][c]

typedef unsigned long long u64;

__device__ __forceinline__ u64 pack2(float lo, float hi) {
    u64 r;
    asm("mov.b64 %0, {%1, %2};" : "=l"(r) : "f"(lo), "f"(hi));
    return r;
}
__device__ __forceinline__ void unpack2(u64 v, float& lo, float& hi) {
    asm("mov.b64 {%0, %1}, %2;" : "=f"(lo), "=f"(hi) : "l"(v));
}
__device__ __forceinline__ u64 fma2(u64 a, u64 b, u64 c) {
    u64 d;
    asm("fma.rn.f32x2 %0, %1, %2, %3;" : "=l"(d) : "l"(a), "l"(b), "l"(c));
    return d;
}

// ---------------------------------------------------------------------------
// Kernel 1: transpose conv weights OIHW -> [kh][kw][ic][oc].
// ---------------------------------------------------------------------------
__global__ void prep_w_kernel(const float* __restrict__ sr_w) {
    int i = blockIdx.x * blockDim.x + threadIdx.x;
    int oc = i & 63;
    int ic = (i >> 6) & 63;
    int kw = (i >> 12) & 7;
    int kh = (i >> 15) & 7;
    g_wT[i] = sr_w[((oc * 64 + ic) * 8 + kh) * 8 + kw];
}

// ---------------------------------------------------------------------------
// Kernel 1b: transpose kv_w and proj_w for coalesced ln_fold reads.
// ---------------------------------------------------------------------------
__global__ void prep_t_kernel(const float* __restrict__ kv_w,
                              const float* __restrict__ proj_w) {
    int i = blockIdx.x * blockDim.x + threadIdx.x;  // 0..8191
    int c = i >> 7, r = i & 127;
    g_kvT[i] = kv_w[r * 64 + c];
    if (i < 4096) {
        int d = i >> 6, tt = i & 63;
        g_pwT[i] = proj_w[tt * 64 + d];
    }
}

// ---------------------------------------------------------------------------
// Kernel 2: 8x8 stride-8 conv + bias. Grid (16, 8), 256 threads.
// ---------------------------------------------------------------------------
__global__ void conv_kernel(const float* __restrict__ x,
                            const float* __restrict__ sr_b) {
    __shared__ float xs[8192];
    __shared__ float ws[4096];

    const int oh = blockIdx.x;
    const int b  = blockIdx.y;
    const int t  = threadIdx.x;
    const int ow = t >> 4;
    const int g  = t & 15;

    float a0 = 0.f, a1 = 0.f, a2 = 0.f, a3 = 0.f;

    for (int kh = 0; kh < 8; kh++) {
        __syncthreads();
        const float4* src =
            (const float4*)(x + ((size_t)(b * NQ + (oh * 8 + kh) * 128)) * C);
        float4* xs4 = (float4*)xs;
        #pragma unroll
        for (int i = t; i < 2048; i += 256) xs4[i] = src[i];

        for (int kw = 0; kw < 8; kw++) {
            __syncthreads();
            const float4* wsrc = (const float4*)(g_wT + (kh * 8 + kw) * 4096);
            float4* ws4 = (float4*)ws;
            #pragma unroll
            for (int i = t; i < 1024; i += 256) ws4[i] = wsrc[i];
            __syncthreads();

            const float* xp = xs + (ow * 8 + kw) * 64;
            const float4* wp = (const float4*)ws + g;
            #pragma unroll 8
            for (int ic = 0; ic < 64; ic++) {
                float xv = xp[ic];
                float4 w4 = wp[ic * 16];
                a0 = fmaf(xv, w4.x, a0);
                a1 = fmaf(xv, w4.y, a1);
                a2 = fmaf(xv, w4.z, a2);
                a3 = fmaf(xv, w4.w, a3);
            }
        }
    }

    int oc = 4 * g;
    float4 o;
    o.x = a0 + sr_b[oc + 0];
    o.y = a1 + sr_b[oc + 1];
    o.z = a2 + sr_b[oc + 2];
    o.w = a3 + sr_b[oc + 3];
    size_t row = (size_t)b * NR + oh * 16 + ow;
    ((float4*)(g_xr + row * C))[g] = o;
}

// ---------------------------------------------------------------------------
// Kernel 3: LN + KV proj + fold, 4 rows per CTA in parallel.
// Grid 512, 256 threads; group g = t>>6 owns row blockIdx.x*4+g, lane tl=t&63.
// ---------------------------------------------------------------------------
__global__ __launch_bounds__(256)
void ln_fold_kernel(const float* __restrict__ ln_g,
                    const float* __restrict__ ln_b,
                    const float* __restrict__ q_w,
                    const float* __restrict__ q_b,
                    const float* __restrict__ kv_b) {
    __shared__ float sy[4][64], sk[4][64], sv[4][64], red[4][4];
    const int t  = threadIdx.x;
    const int g  = t >> 6;
    const int tl = t & 63;
    const int row = blockIdx.x * 4 + g;  // 0..2047

    float v = g_xr[row * 64 + tl];

    float s = v, sq = v * v;
    #pragma unroll
    for (int off = 16; off > 0; off >>= 1) {
        s  += __shfl_xor_sync(0xffffffffu, s, off);
        sq += __shfl_xor_sync(0xffffffffu, sq, off);
    }
    if ((tl & 31) == 0) {
        red[g][tl >> 5]     = s;
        red[g][2 + (tl >> 5)] = sq;
    }
    __syncthreads();
    float mu  = (red[g][0] + red[g][1]) * (1.0f / 64.0f);
    float var = (red[g][2] + red[g][3]) * (1.0f / 64.0f) - mu * mu;
    float y   = (v - mu) * rsqrtf(var + 1e-5f) * ln_g[tl] + ln_b[tl];
    sy[g][tl] = y;
    __syncthreads();

    float kd = kv_b[tl], vd = kv_b[64 + tl];
    #pragma unroll 8
    for (int c = 0; c < 64; c++) {
        kd = fmaf(sy[g][c], g_kvT[c * 128 + tl], kd);
        vd = fmaf(sy[g][c], g_kvT[c * 128 + 64 + tl], vd);
    }
    sk[g][tl] = kd;
    sv[g][tl] = vd;
    __syncthreads();

    float kt = 0.f, wv = 0.f;
    #pragma unroll 8
    for (int d = 0; d < 64; d++) {
        kt = fmaf(sk[g][d], q_w[d * 64 + tl], kt);
        wv = fmaf(sv[g][d], g_pwT[d * 64 + tl], wv);
    }
    g_KtT[(row >> 8) * (64 * 256) + tl * 256 + (row & 255)] = kt * SCALEF;
    g_Wv[row * 64 + tl] = wv;
    if (tl == 0) {
        float kb = 0.f;
        #pragma unroll 8
        for (int d = 0; d < 64; d++) kb = fmaf(q_b[d], sk[g][d], kb);
        g_kb[row] = kb * SCALEF;
    }
}

// ---------------------------------------------------------------------------
// Kernel 4: attention (unchanged from the verified 374.9us run).
// CTA 64 rows, 128 thr, grid (256,8), 2 j-chunks of 128, 2 CTAs/SM.
// ---------------------------------------------------------------------------
#define SM_X   0
#define SM_KT  4352
#define SM_WC  12800
#define SM_DEN 21504
#define SM_KB  21568
#define SM_PB  21824
#define ATTN_SMEM_FLOATS 21888
#define ATTN_SMEM_BYTES  (ATTN_SMEM_FLOATS * 4)

__global__ __launch_bounds__(128, 2)
void attn_kernel(const float* __restrict__ x,
                 const float* __restrict__ proj_b,
                 float* __restrict__ out) {
    extern __shared__ float sm[];
    float* sX   = sm + SM_X;
    float* sKtT = sm + SM_KT;
    float* sPB  = sm + SM_KT;   // P alias
    float* sWc  = sm + SM_WC;
    float* sden = sm + SM_DEN;
    float* skb  = sm + SM_KB;
    float* spb  = sm + SM_PB;

    const int t    = threadIdx.x;
    const int tile = blockIdx.x;
    const int b    = blockIdx.y;

    const int rg  = t >> 4;
    const int jg  = t & 15;
    const int cg2 = t & 15;

    {
        const float4* gx =
            (const float4*)(x + ((size_t)b * NQ + (size_t)tile * 64) * C);
        #pragma unroll
        for (int n = 0; n < 8; n++) {
            int e = t + n * 128;
            int row = e >> 4, kq = e & 15;
            float4 v = gx[e];
            *(float4*)&sX[row * 68 + ((kq ^ (row >> 3)) << 2)] = v;
        }
        skb[t]       = g_kb[b * NR + t];
        skb[t + 128] = g_kb[b * NR + t + 128];
        if (t < 64) spb[t] = proj_b[t];
    }

    const int jb0 = jg * 2,      qb0 = jb0 ^ (jb0 >> 3);
    const int jb1 = jg * 2 + 1,  qb1 = jb1 ^ (jb1 >> 3);
    const int qc  = cg2 ^ (cg2 >> 3);

    u64 o2[8][2];
    #pragma unroll
    for (int i = 0; i < 8; i++) { o2[i][0] = 0ull; o2[i][1] = 0ull; }
    float dsum[8];
    #pragma unroll
    for (int i = 0; i < 8; i++) dsum[i] = 0.f;

    const float* gktB = g_KtT + (size_t)b * C * NR;
    const float* gwB  = g_Wv + (size_t)b * NR * C;

    #pragma unroll 1
    for (int c = 0; c < 2; c++) {
        #pragma unroll
        for (int n = 0; n < 16; n++) {
            int e = t + n * 128;
            int k  = e >> 5, jbs = e & 31;
            float4 kv = *(const float4*)(gktB + k * 256 + c * 128 + jbs * 4);
            *(float4*)&sKtT[k * 132 + ((jbs ^ (jbs >> 3)) << 2)] = kv;
            int j  = e >> 4, cbs = e & 15;
            float4 wv =
                *(const float4*)(gwB + ((size_t)c * 128 + j) * 64 + cbs * 4);
            *(float4*)&sWc[j * 68 + ((cbs ^ (cbs >> 3)) << 2)] = wv;
        }
        __syncthreads();

        u64 s2[8][4];
        #pragma unroll
        for (int i = 0; i < 8; i++)
            #pragma unroll
            for (int q = 0; q < 4; q++) s2[i][q] = 0ull;

        #pragma unroll 1
        for (int kq = 0; kq < 16; kq++) {
            float4 xq[8];
            #pragma unroll
            for (int i = 0; i < 8; i++)
                xq[i] =
                    *(const float4*)&sX[(rg * 8 + i) * 68 + ((kq ^ rg) << 2)];
            #pragma unroll
            for (int kk = 0; kk < 4; kk++) {
                int k = kq * 4 + kk;
                ulonglong2 k01 = *(const ulonglong2*)&sKtT[k * 132 + (qb0 << 2)];
                ulonglong2 k23 = *(const ulonglong2*)&sKtT[k * 132 + (qb1 << 2)];
                #pragma unroll
                for (int i = 0; i < 8; i++) {
                    float xv = ((const float*)&xq[i])[kk];
                    u64 xp = pack2(xv, xv);
                    s2[i][0] = fma2(xp, k01.x, s2[i][0]);
                    s2[i][1] = fma2(xp, k01.y, s2[i][1]);
                    s2[i][2] = fma2(xp, k23.x, s2[i][2]);
                    s2[i][3] = fma2(xp, k23.y, s2[i][3]);
                }
            }
        }
        __syncthreads();

        #pragma unroll
        for (int mp = 0; mp < 4; mp++) {
            int jl  = jg * 8 + 2 * mp;
            float kb0 = skb[c * 128 + jl];
            float kb1 = skb[c * 128 + jl + 1];
            int jbp = jl >> 2;
            int wof = (jl & 3);
            #pragma unroll
            for (int i = 0; i < 8; i++) {
                float sa, sb;
                unpack2(s2[i][mp], sa, sb);
                float e0 = __expf(sa + kb0);
                float e1 = __expf(sb + kb1);
                dsum[i] += e0 + e1;
                int row = rg * 8 + i;
                int pp = jbp ^ rg ^ (((jbp >> 4) & 1) << 2);
                *(u64*)&sPB[row * 132 + (pp << 2) + wof] = pack2(e0, e1);
            }
        }
        __syncthreads();

        #pragma unroll 1
        for (int jq = 0; jq < 32; jq++) {
            int pp = jq ^ rg ^ (((jq >> 4) & 1) << 2);
            float4 p4[8];
            #pragma unroll
            for (int i = 0; i < 8; i++)
                p4[i] = *(const float4*)&sPB[(rg * 8 + i) * 132 + (pp << 2)];
            #pragma unroll
            for (int jj = 0; jj < 4; jj++) {
                int j = jq * 4 + jj;
                ulonglong2 w2 = *(const ulonglong2*)&sWc[j * 68 + (qc << 2)];
                #pragma unroll
                for (int i = 0; i < 8; i++) {
                    float pv = ((const float*)&p4[i])[jj];
                    u64 pk = pack2(pv, pv);
                    o2[i][0] = fma2(pk, w2.x, o2[i][0]);
                    o2[i][1] = fma2(pk, w2.y, o2[i][1]);
                }
            }
        }
        __syncthreads();
    }

    #pragma unroll
    for (int i = 0; i < 8; i++) {
        #pragma unroll
        for (int off = 1; off < 16; off <<= 1)
            dsum[i] += __shfl_xor_sync(0xffffffffu, dsum[i], off);
    }
    if (jg == 0) {
        #pragma unroll
        for (int i = 0; i < 8; i++) sden[rg * 8 + i] = dsum[i];
    }
    __syncthreads();

    #pragma unroll
    for (int i = 0; i < 8; i++) {
        int row = rg * 8 + i;
        float inv = 1.0f / sden[row];
        float e0, e1, e2, e3;
        unpack2(o2[i][0], e0, e1);
        unpack2(o2[i][1], e2, e3);
        const float* pb = spb + cg2 * 4;
        float4 r0;
        r0.x = fmaf(e0, inv, pb[0]);
        r0.y = fmaf(e1, inv, pb[1]);
        r0.z = fmaf(e2, inv, pb[2]);
        r0.w = fmaf(e3, inv, pb[3]);
        *(float4*)(out +
            ((size_t)b * NQ + (size_t)tile * 64 + row) * C + cg2 * 4) = r0;
    }
}

// ---------------------------------------------------------------------------
extern "C" void kernel_launch(void* const* d_in, const int* in_sizes, int n_in,
                              void* d_out, int out_size) {
    const float* x      = (const float*)d_in[0];
    const float* sr_w   = (const float*)d_in[1];
    const float* sr_b   = (const float*)d_in[2];
    const float* ln_g   = (const float*)d_in[3];
    const float* ln_b   = (const float*)d_in[4];
    const float* q_w    = (const float*)d_in[5];
    const float* q_b    = (const float*)d_in[6];
    const float* kv_w   = (const float*)d_in[7];
    const float* kv_b   = (const float*)d_in[8];
    const float* proj_w = (const float*)d_in[9];
    const float* proj_b = (const float*)d_in[10];
    float* out = (float*)d_out;

    static bool attr_set = false;
    if (!attr_set) {
        cudaFuncSetAttribute(attn_kernel,
                             cudaFuncAttributeMaxDynamicSharedMemorySize,
                             ATTN_SMEM_BYTES);
        attr_set = true;
    }

    prep_w_kernel<<<256, 1024>>>(sr_w);
    prep_t_kernel<<<8, 1024>>>(kv_w, proj_w);
    conv_kernel<<<dim3(16, 8), 256>>>(x, sr_b);
    ln_fold_kernel<<<512, 256>>>(ln_g, ln_b, q_w, q_b, kv_b);
    attn_kernel<<<dim3(256, 8), 128, ATTN_SMEM_BYTES>>>(x, proj_b, out);
}

// round 16
// speedup vs baseline: 2.4278x; 1.0249x over previous
#include <cuda_runtime.h>
#include <cstdint>

#define BATCH 8
#define NQ    16384
#define C     64
#define NR    256
#define SCALEF 0.125f

__device__ float g_wT[64 * 64 * 64];     // conv weights [kh*8+kw][ic][oc]
__device__ float g_kvT[64 * 128];        // kv_w transposed: [c][r]
__device__ float g_pwT[64 * 64];         // proj_w transposed: [d][t]
__device__ float g_xr[BATCH * NR * C];   // conv output (pre-LN)
__device__ float g_KtT[BATCH * C * NR];  // folded+scaled K, transposed [b][c][j]
__device__ float g_kb[BATCH * NR];       // folded+scaled bias
__device__ float g_Wv[BATCH * NR * C];   // folded V [b][j][c]

typedef unsigned long long u64;

__device__ __forceinline__ u64 pack2(float lo, float hi) {
    u64 r;
    asm("mov.b64 %0, {%1, %2};" : "=l"(r) : "f"(lo), "f"(hi));
    return r;
}
__device__ __forceinline__ void unpack2(u64 v, float& lo, float& hi) {
    asm("mov.b64 {%0, %1}, %2;" : "=f"(lo), "=f"(hi) : "l"(v));
}
__device__ __forceinline__ u64 fma2(u64 a, u64 b, u64 c) {
    u64 d;
    asm("fma.rn.f32x2 %0, %1, %2, %3;" : "=l"(d) : "l"(a), "l"(b), "l"(c));
    return d;
}

// ---------------------------------------------------------------------------
// Kernel 1: transpose conv weights OIHW -> [kh][kw][ic][oc].
// ---------------------------------------------------------------------------
__global__ void prep_w_kernel(const float* __restrict__ sr_w) {
    int i = blockIdx.x * blockDim.x + threadIdx.x;
    int oc = i & 63;
    int ic = (i >> 6) & 63;
    int kw = (i >> 12) & 7;
    int kh = (i >> 15) & 7;
    g_wT[i] = sr_w[((oc * 64 + ic) * 8 + kh) * 8 + kw];
}

// ---------------------------------------------------------------------------
// Kernel 1b: transpose kv_w and proj_w for coalesced ln_fold reads.
// ---------------------------------------------------------------------------
__global__ void prep_t_kernel(const float* __restrict__ kv_w,
                              const float* __restrict__ proj_w) {
    int i = blockIdx.x * blockDim.x + threadIdx.x;  // 0..8191
    int c = i >> 7, r = i & 127;
    g_kvT[i] = kv_w[r * 64 + c];
    if (i < 4096) {
        int d = i >> 6, tt = i & 63;
        g_pwT[i] = proj_w[tt * 64 + d];
    }
}

// ---------------------------------------------------------------------------
// Kernel 2: 8x8 stride-8 conv + bias. Grid (16, 8), 256 threads.
// ---------------------------------------------------------------------------
__global__ void conv_kernel(const float* __restrict__ x,
                            const float* __restrict__ sr_b) {
    __shared__ float xs[8192];
    __shared__ float ws[4096];

    const int oh = blockIdx.x;
    const int b  = blockIdx.y;
    const int t  = threadIdx.x;
    const int ow = t >> 4;
    const int g  = t & 15;

    float a0 = 0.f, a1 = 0.f, a2 = 0.f, a3 = 0.f;

    for (int kh = 0; kh < 8; kh++) {
        __syncthreads();
        const float4* src =
            (const float4*)(x + ((size_t)(b * NQ + (oh * 8 + kh) * 128)) * C);
        float4* xs4 = (float4*)xs;
        #pragma unroll
        for (int i = t; i < 2048; i += 256) xs4[i] = src[i];

        for (int kw = 0; kw < 8; kw++) {
            __syncthreads();
            const float4* wsrc = (const float4*)(g_wT + (kh * 8 + kw) * 4096);
            float4* ws4 = (float4*)ws;
            #pragma unroll
            for (int i = t; i < 1024; i += 256) ws4[i] = wsrc[i];
            __syncthreads();

            const float* xp = xs + (ow * 8 + kw) * 64;
            const float4* wp = (const float4*)ws + g;
            #pragma unroll 8
            for (int ic = 0; ic < 64; ic++) {
                float xv = xp[ic];
                float4 w4 = wp[ic * 16];
                a0 = fmaf(xv, w4.x, a0);
                a1 = fmaf(xv, w4.y, a1);
                a2 = fmaf(xv, w4.z, a2);
                a3 = fmaf(xv, w4.w, a3);
            }
        }
    }

    int oc = 4 * g;
    float4 o;
    o.x = a0 + sr_b[oc + 0];
    o.y = a1 + sr_b[oc + 1];
    o.z = a2 + sr_b[oc + 2];
    o.w = a3 + sr_b[oc + 3];
    size_t row = (size_t)b * NR + oh * 16 + ow;
    ((float4*)(g_xr + row * C))[g] = o;
}

// ---------------------------------------------------------------------------
// Kernel 3: LN + KV proj + fold, 4 rows per CTA in parallel. Grid 512 x 256.
// ---------------------------------------------------------------------------
__global__ __launch_bounds__(256)
void ln_fold_kernel(const float* __restrict__ ln_g,
                    const float* __restrict__ ln_b,
                    const float* __restrict__ q_w,
                    const float* __restrict__ q_b,
                    const float* __restrict__ kv_b) {
    __shared__ float sy[4][64], sk[4][64], sv[4][64], red[4][4];
    const int t  = threadIdx.x;
    const int g  = t >> 6;
    const int tl = t & 63;
    const int row = blockIdx.x * 4 + g;  // 0..2047

    float v = g_xr[row * 64 + tl];

    float s = v, sq = v * v;
    #pragma unroll
    for (int off = 16; off > 0; off >>= 1) {
        s  += __shfl_xor_sync(0xffffffffu, s, off);
        sq += __shfl_xor_sync(0xffffffffu, sq, off);
    }
    if ((tl & 31) == 0) {
        red[g][tl >> 5]       = s;
        red[g][2 + (tl >> 5)] = sq;
    }
    __syncthreads();
    float mu  = (red[g][0] + red[g][1]) * (1.0f / 64.0f);
    float var = (red[g][2] + red[g][3]) * (1.0f / 64.0f) - mu * mu;
    float y   = (v - mu) * rsqrtf(var + 1e-5f) * ln_g[tl] + ln_b[tl];
    sy[g][tl] = y;
    __syncthreads();

    float kd = kv_b[tl], vd = kv_b[64 + tl];
    #pragma unroll 8
    for (int c = 0; c < 64; c++) {
        kd = fmaf(sy[g][c], g_kvT[c * 128 + tl], kd);
        vd = fmaf(sy[g][c], g_kvT[c * 128 + 64 + tl], vd);
    }
    sk[g][tl] = kd;
    sv[g][tl] = vd;
    __syncthreads();

    float kt = 0.f, wv = 0.f;
    #pragma unroll 8
    for (int d = 0; d < 64; d++) {
        kt = fmaf(sk[g][d], q_w[d * 64 + tl], kt);
        wv = fmaf(sv[g][d], g_pwT[d * 64 + tl], wv);
    }
    g_KtT[(row >> 8) * (64 * 256) + tl * 256 + (row & 255)] = kt * SCALEF;
    g_Wv[row * 64 + tl] = wv;
    if (tl == 0) {
        float kb = 0.f;
        #pragma unroll 8
        for (int d = 0; d < 64; d++) kb = fmaf(q_b[d], sk[g][d], kb);
        g_kb[row] = kb * SCALEF;
    }
}

// ---------------------------------------------------------------------------
// Kernel 4: attention. CTA 64 rows, 128 thr, grid (256,8), 3 CTAs/SM.
// 2 j-chunks of 128; Wv staged in two 64-j halves (smem 70.1KB).
// pass1: rg=t>>4 rows rg*8..+7, jg=t&15 j jg*8..+7 (s2[8][4] j-packed)
// pass2: rg rows, cg2=t&15 ch cg2*4..+3, two 64-j segments
// smem: sX[64*68] | sKtT[64*132] (P alias) | sWcH[64*68] | den kb pb
// ---------------------------------------------------------------------------
#define SM_X   0
#define SM_KT  4352
#define SM_WC  12800
#define SM_DEN 17152
#define SM_KB  17216
#define SM_PB  17472
#define ATTN_SMEM_FLOATS 17536
#define ATTN_SMEM_BYTES  (ATTN_SMEM_FLOATS * 4)

__global__ __launch_bounds__(128, 3)
void attn_kernel(const float* __restrict__ x,
                 const float* __restrict__ proj_b,
                 float* __restrict__ out) {
    extern __shared__ float sm[];
    float* sX   = sm + SM_X;
    float* sKtT = sm + SM_KT;
    float* sPB  = sm + SM_KT;   // P alias
    float* sWcH = sm + SM_WC;   // current 64-j half of Wv
    float* sden = sm + SM_DEN;
    float* skb  = sm + SM_KB;
    float* spb  = sm + SM_PB;

    const int t    = threadIdx.x;
    const int tile = blockIdx.x;
    const int b    = blockIdx.y;

    const int rg  = t >> 4;
    const int jg  = t & 15;
    const int cg2 = t & 15;

    {
        const float4* gx =
            (const float4*)(x + ((size_t)b * NQ + (size_t)tile * 64) * C);
        #pragma unroll
        for (int n = 0; n < 8; n++) {
            int e = t + n * 128;
            int row = e >> 4, kq = e & 15;
            float4 v = gx[e];
            *(float4*)&sX[row * 68 + ((kq ^ (row >> 3)) << 2)] = v;
        }
        skb[t]       = g_kb[b * NR + t];
        skb[t + 128] = g_kb[b * NR + t + 128];
        if (t < 64) spb[t] = proj_b[t];
    }

    const int jb0 = jg * 2,      qb0 = jb0 ^ (jb0 >> 3);
    const int jb1 = jg * 2 + 1,  qb1 = jb1 ^ (jb1 >> 3);
    const int qc  = cg2 ^ (cg2 >> 3);

    u64 o2[8][2];
    #pragma unroll
    for (int i = 0; i < 8; i++) { o2[i][0] = 0ull; o2[i][1] = 0ull; }
    float dsum[8];
    #pragma unroll
    for (int i = 0; i < 8; i++) dsum[i] = 0.f;

    const float* gktB = g_KtT + (size_t)b * C * NR;
    const float* gwB  = g_Wv + (size_t)b * NR * C;

    #pragma unroll 1
    for (int c = 0; c < 2; c++) {
        // ---- stage Kt chunk [64k][128j] + Wv half 0 [64j][64ch] ----
        #pragma unroll
        for (int n = 0; n < 16; n++) {
            int e = t + n * 128;
            int k  = e >> 5, jbs = e & 31;
            float4 kv = *(const float4*)(gktB + k * 256 + c * 128 + jbs * 4);
            *(float4*)&sKtT[k * 132 + ((jbs ^ (jbs >> 3)) << 2)] = kv;
        }
        #pragma unroll
        for (int n = 0; n < 8; n++) {
            int e = t + n * 128;
            int j = e >> 4, cbs = e & 15;
            float4 wv =
                *(const float4*)(gwB + ((size_t)c * 128 + j) * 64 + cbs * 4);
            *(float4*)&sWcH[j * 68 + ((cbs ^ (cbs >> 3)) << 2)] = wv;
        }
        __syncthreads();

        // ===== pass 1: S[8r][8j] = X @ Kt^T (K block hoisted per kq) =====
        u64 s2[8][4];
        #pragma unroll
        for (int i = 0; i < 8; i++)
            #pragma unroll
            for (int q = 0; q < 4; q++) s2[i][q] = 0ull;

        #pragma unroll 1
        for (int kq = 0; kq < 16; kq++) {
            ulonglong2 ka[4], kbv[4];
            #pragma unroll
            for (int kk = 0; kk < 4; kk++) {
                int k = kq * 4 + kk;
                ka[kk]  = *(const ulonglong2*)&sKtT[k * 132 + (qb0 << 2)];
                kbv[kk] = *(const ulonglong2*)&sKtT[k * 132 + (qb1 << 2)];
            }
            #pragma unroll
            for (int i = 0; i < 8; i++) {
                float4 x4 =
                    *(const float4*)&sX[(rg * 8 + i) * 68 + ((kq ^ rg) << 2)];
                #pragma unroll
                for (int kk = 0; kk < 4; kk++) {
                    float xv = ((const float*)&x4)[kk];
                    u64 xp = pack2(xv, xv);
                    s2[i][0] = fma2(xp, ka[kk].x, s2[i][0]);
                    s2[i][1] = fma2(xp, ka[kk].y, s2[i][1]);
                    s2[i][2] = fma2(xp, kbv[kk].x, s2[i][2]);
                    s2[i][3] = fma2(xp, kbv[kk].y, s2[i][3]);
                }
            }
        }
        __syncthreads();  // all Kt reads done (sPB aliases sKtT)

        // ---- exp + kb, accumulate den, store P (swizzled) ----
        #pragma unroll
        for (int mp = 0; mp < 4; mp++) {
            int jl  = jg * 8 + 2 * mp;
            float kb0 = skb[c * 128 + jl];
            float kb1 = skb[c * 128 + jl + 1];
            int jbp = jl >> 2;
            int wof = (jl & 3);
            #pragma unroll
            for (int i = 0; i < 8; i++) {
                float sa, sb;
                unpack2(s2[i][mp], sa, sb);
                float e0 = __expf(sa + kb0);
                float e1 = __expf(sb + kb1);
                dsum[i] += e0 + e1;
                int row = rg * 8 + i;
                int pp = jbp ^ rg ^ (((jbp >> 4) & 1) << 2);
                *(u64*)&sPB[row * 132 + (pp << 2) + wof] = pack2(e0, e1);
            }
        }
        __syncthreads();  // P complete; W half 0 staged

        // ===== pass 2 over two 64-j segments =====
        #pragma unroll 1
        for (int seg = 0; seg < 2; seg++) {
            if (seg == 1) {
                __syncthreads();  // seg-0 reads of sWcH done
                #pragma unroll
                for (int n = 0; n < 8; n++) {
                    int e = t + n * 128;
                    int j = e >> 4, cbs = e & 15;
                    float4 wv = *(const float4*)(gwB +
                        ((size_t)c * 128 + 64 + j) * 64 + cbs * 4);
                    *(float4*)&sWcH[j * 68 + ((cbs ^ (cbs >> 3)) << 2)] = wv;
                }
                __syncthreads();
            }
            #pragma unroll 1
            for (int jq = seg * 16; jq < seg * 16 + 16; jq++) {
                int pp = jq ^ rg ^ (((jq >> 4) & 1) << 2);
                float4 p4[8];
                #pragma unroll
                for (int i = 0; i < 8; i++)
                    p4[i] =
                        *(const float4*)&sPB[(rg * 8 + i) * 132 + (pp << 2)];
                #pragma unroll
                for (int jj = 0; jj < 4; jj++) {
                    int jloc = (jq - seg * 16) * 4 + jj;
                    ulonglong2 w2 =
                        *(const ulonglong2*)&sWcH[jloc * 68 + (qc << 2)];
                    #pragma unroll
                    for (int i = 0; i < 8; i++) {
                        float pv = ((const float*)&p4[i])[jj];
                        u64 pk = pack2(pv, pv);
                        o2[i][0] = fma2(pk, w2.x, o2[i][0]);
                        o2[i][1] = fma2(pk, w2.y, o2[i][1]);
                    }
                }
            }
        }
        __syncthreads();  // sPB(KtT)/sWcH reused next chunk
    }

    // ---- den: reduce across the 16 jg lanes, publish to smem ----
    #pragma unroll
    for (int i = 0; i < 8; i++) {
        #pragma unroll
        for (int off = 1; off < 16; off <<= 1)
            dsum[i] += __shfl_xor_sync(0xffffffffu, dsum[i], off);
    }
    if (jg == 0) {
        #pragma unroll
        for (int i = 0; i < 8; i++) sden[rg * 8 + i] = dsum[i];
    }
    __syncthreads();

    // ---- epilogue: out = o2/den + proj_b (thread owns 8 rows x 4 ch) ----
    #pragma unroll
    for (int i = 0; i < 8; i++) {
        int row = rg * 8 + i;
        float inv = 1.0f / sden[row];
        float e0, e1, e2, e3;
        unpack2(o2[i][0], e0, e1);
        unpack2(o2[i][1], e2, e3);
        const float* pb = spb + cg2 * 4;
        float4 r0;
        r0.x = fmaf(e0, inv, pb[0]);
        r0.y = fmaf(e1, inv, pb[1]);
        r0.z = fmaf(e2, inv, pb[2]);
        r0.w = fmaf(e3, inv, pb[3]);
        *(float4*)(out +
            ((size_t)b * NQ + (size_t)tile * 64 + row) * C + cg2 * 4) = r0;
    }
}

// ---------------------------------------------------------------------------
extern "C" void kernel_launch(void* const* d_in, const int* in_sizes, int n_in,
                              void* d_out, int out_size) {
    const float* x      = (const float*)d_in[0];
    const float* sr_w   = (const float*)d_in[1];
    const float* sr_b   = (const float*)d_in[2];
    const float* ln_g   = (const float*)d_in[3];
    const float* ln_b   = (const float*)d_in[4];
    const float* q_w    = (const float*)d_in[5];
    const float* q_b    = (const float*)d_in[6];
    const float* kv_w   = (const float*)d_in[7];
    const float* kv_b   = (const float*)d_in[8];
    const float* proj_w = (const float*)d_in[9];
    const float* proj_b = (const float*)d_in[10];
    float* out = (float*)d_out;

    static bool attr_set = false;
    if (!attr_set) {
        cudaFuncSetAttribute(attn_kernel,
                             cudaFuncAttributeMaxDynamicSharedMemorySize,
                             ATTN_SMEM_BYTES);
        attr_set = true;
    }

    prep_w_kernel<<<256, 1024>>>(sr_w);
    prep_t_kernel<<<8, 1024>>>(kv_w, proj_w);
    conv_kernel<<<dim3(16, 8), 256>>>(x, sr_b);
    ln_fold_kernel<<<512, 256>>>(ln_g, ln_b, q_w, q_b, kv_b);
    attn_kernel<<<dim3(256, 8), 128, ATTN_SMEM_BYTES>>>(x, proj_b, out);
}

// round 17
// speedup vs baseline: 2.6514x; 1.0921x over previous
#include <cuda_runtime.h>
#include <cstdint>

#define BATCH 8
#define NQ    16384
#define C     64
#define NR    256
#define SCALEF 0.125f

__device__ float g_wT[64 * 64 * 64];     // conv weights [kh*8+kw][ic][oc]
__device__ float g_kvT[64 * 128];        // kv_w transposed: [c][r]
__device__ float g_pwT[64 * 64];         // proj_w transposed: [d][t]
__device__ float g_xr[BATCH * NR * C];   // conv output (pre-LN)
__device__ float g_KtT[BATCH * C * NR];  // folded+scaled K, transposed [b][c][j]
__device__ float g_kb[BATCH * NR];       // folded+scaled bias
__device__ float g_Wv[BATCH * NR * C];   // folded V [b][j][c]

__device__ __forceinline__ uint32_t f2tf(float x) {
    uint32_t r;
    asm("cvt.rna.tf32.f32 %0, %1;" : "=r"(r) : "f"(x));
    return r;
}

// D += A@B, m16n8k8 tf32 (A row-major frag, B col-major frag)
__device__ __forceinline__ void mma8(float* c, const uint32_t* a,
                                     uint32_t b0, uint32_t b1) {
    asm volatile(
        "mma.sync.aligned.m16n8k8.row.col.f32.tf32.tf32.f32 "
        "{%0,%1,%2,%3}, {%4,%5,%6,%7}, {%8,%9}, {%0,%1,%2,%3};"
        : "+f"(c[0]), "+f"(c[1]), "+f"(c[2]), "+f"(c[3])
        : "r"(a[0]), "r"(a[1]), "r"(a[2]), "r"(a[3]), "r"(b0), "r"(b1));
}

// ---------------------------------------------------------------------------
// Kernel 1: transpose conv weights OIHW -> [kh][kw][ic][oc].
// ---------------------------------------------------------------------------
__global__ void prep_w_kernel(const float* __restrict__ sr_w) {
    int i = blockIdx.x * blockDim.x + threadIdx.x;
    int oc = i & 63;
    int ic = (i >> 6) & 63;
    int kw = (i >> 12) & 7;
    int kh = (i >> 15) & 7;
    g_wT[i] = sr_w[((oc * 64 + ic) * 8 + kh) * 8 + kw];
}

// ---------------------------------------------------------------------------
// Kernel 1b: transpose kv_w and proj_w for coalesced ln_fold reads.
// ---------------------------------------------------------------------------
__global__ void prep_t_kernel(const float* __restrict__ kv_w,
                              const float* __restrict__ proj_w) {
    int i = blockIdx.x * blockDim.x + threadIdx.x;  // 0..8191
    int c = i >> 7, r = i & 127;
    g_kvT[i] = kv_w[r * 64 + c];
    if (i < 4096) {
        int d = i >> 6, tt = i & 63;
        g_pwT[i] = proj_w[tt * 64 + d];
    }
}

// ---------------------------------------------------------------------------
// Kernel 2: 8x8 stride-8 conv + bias. Grid (16, 8), 256 threads.
// ---------------------------------------------------------------------------
__global__ void conv_kernel(const float* __restrict__ x,
                            const float* __restrict__ sr_b) {
    __shared__ float xs[8192];
    __shared__ float ws[4096];

    const int oh = blockIdx.x;
    const int b  = blockIdx.y;
    const int t  = threadIdx.x;
    const int ow = t >> 4;
    const int g  = t & 15;

    float a0 = 0.f, a1 = 0.f, a2 = 0.f, a3 = 0.f;

    for (int kh = 0; kh < 8; kh++) {
        __syncthreads();
        const float4* src =
            (const float4*)(x + ((size_t)(b * NQ + (oh * 8 + kh) * 128)) * C);
        float4* xs4 = (float4*)xs;
        #pragma unroll
        for (int i = t; i < 2048; i += 256) xs4[i] = src[i];

        for (int kw = 0; kw < 8; kw++) {
            __syncthreads();
            const float4* wsrc = (const float4*)(g_wT + (kh * 8 + kw) * 4096);
            float4* ws4 = (float4*)ws;
            #pragma unroll
            for (int i = t; i < 1024; i += 256) ws4[i] = wsrc[i];
            __syncthreads();

            const float* xp = xs + (ow * 8 + kw) * 64;
            const float4* wp = (const float4*)ws + g;
            #pragma unroll 8
            for (int ic = 0; ic < 64; ic++) {
                float xv = xp[ic];
                float4 w4 = wp[ic * 16];
                a0 = fmaf(xv, w4.x, a0);
                a1 = fmaf(xv, w4.y, a1);
                a2 = fmaf(xv, w4.z, a2);
                a3 = fmaf(xv, w4.w, a3);
            }
        }
    }

    int oc = 4 * g;
    float4 o;
    o.x = a0 + sr_b[oc + 0];
    o.y = a1 + sr_b[oc + 1];
    o.z = a2 + sr_b[oc + 2];
    o.w = a3 + sr_b[oc + 3];
    size_t row = (size_t)b * NR + oh * 16 + ow;
    ((float4*)(g_xr + row * C))[g] = o;
}

// ---------------------------------------------------------------------------
// Kernel 3: LN + KV proj + fold, 4 rows per CTA in parallel. Grid 512 x 256.
// ---------------------------------------------------------------------------
__global__ __launch_bounds__(256)
void ln_fold_kernel(const float* __restrict__ ln_g,
                    const float* __restrict__ ln_b,
                    const float* __restrict__ q_w,
                    const float* __restrict__ q_b,
                    const float* __restrict__ kv_b) {
    __shared__ float sy[4][64], sk[4][64], sv[4][64], red[4][4];
    const int t  = threadIdx.x;
    const int g  = t >> 6;
    const int tl = t & 63;
    const int row = blockIdx.x * 4 + g;  // 0..2047

    float v = g_xr[row * 64 + tl];

    float s = v, sq = v * v;
    #pragma unroll
    for (int off = 16; off > 0; off >>= 1) {
        s  += __shfl_xor_sync(0xffffffffu, s, off);
        sq += __shfl_xor_sync(0xffffffffu, sq, off);
    }
    if ((tl & 31) == 0) {
        red[g][tl >> 5]       = s;
        red[g][2 + (tl >> 5)] = sq;
    }
    __syncthreads();
    float mu  = (red[g][0] + red[g][1]) * (1.0f / 64.0f);
    float var = (red[g][2] + red[g][3]) * (1.0f / 64.0f) - mu * mu;
    float y   = (v - mu) * rsqrtf(var + 1e-5f) * ln_g[tl] + ln_b[tl];
    sy[g][tl] = y;
    __syncthreads();

    float kd = kv_b[tl], vd = kv_b[64 + tl];
    #pragma unroll 8
    for (int c = 0; c < 64; c++) {
        kd = fmaf(sy[g][c], g_kvT[c * 128 + tl], kd);
        vd = fmaf(sy[g][c], g_kvT[c * 128 + 64 + tl], vd);
    }
    sk[g][tl] = kd;
    sv[g][tl] = vd;
    __syncthreads();

    float kt = 0.f, wv = 0.f;
    #pragma unroll 8
    for (int d = 0; d < 64; d++) {
        kt = fmaf(sk[g][d], q_w[d * 64 + tl], kt);
        wv = fmaf(sv[g][d], g_pwT[d * 64 + tl], wv);
    }
    g_KtT[(row >> 8) * (64 * 256) + tl * 256 + (row & 255)] = kt * SCALEF;
    g_Wv[row * 64 + tl] = wv;
    if (tl == 0) {
        float kb = 0.f;
        #pragma unroll 8
        for (int d = 0; d < 64; d++) kb = fmaf(q_b[d], sk[g][d], kb);
        g_kb[row] = kb * SCALEF;
    }
}

// ---------------------------------------------------------------------------
// Kernel 4: attention via mma.sync m16n8k8 tf32, tf32x3 (hi/lo split on both
// operands, 3 MMAs: hh + lh + hl). CTA = 64 rows, 128 thr (4 warps), grid
// (256,8), 4 j-chunks of 64. Warp w owns rows 16w..16w+15.
// Smem (floats): Xhi[64*68] Xlo[64*68] KThi[64*72] KTlo[64*72] (P aliases KT)
//   WChi[64*72] WClo[64*72] den[64] kb[256] pb[64]   -> 110080 B, 2 CTAs/SM.
// ---------------------------------------------------------------------------
#define AS_XHI 0
#define AS_XLO 4352
#define AS_KTH 8704
#define AS_KTL 13312
#define AS_WCH 17920
#define AS_WCL 22528
#define AS_DEN 27136
#define AS_KB  27200
#define AS_PB  27456
#define ATTN_SMEM_FLOATS 27520
#define ATTN_SMEM_BYTES  (ATTN_SMEM_FLOATS * 4)

__global__ __launch_bounds__(128)
void attn_kernel(const float* __restrict__ x,
                 const float* __restrict__ proj_b,
                 float* __restrict__ out) {
    extern __shared__ float sm[];
    uint32_t* uXH = (uint32_t*)(sm + AS_XHI);
    uint32_t* uXL = (uint32_t*)(sm + AS_XLO);
    uint32_t* uKH = (uint32_t*)(sm + AS_KTH);
    uint32_t* uKL = (uint32_t*)(sm + AS_KTL);
    uint32_t* uPH = uKH;   // P aliases KT (barrier-separated)
    uint32_t* uPL = uKL;
    uint32_t* uWH = (uint32_t*)(sm + AS_WCH);
    uint32_t* uWL = (uint32_t*)(sm + AS_WCL);

    const int t    = threadIdx.x;
    const int tile = blockIdx.x;   // 0..255
    const int b    = blockIdx.y;   // 0..7
    const int w    = t >> 5;
    const int li   = t & 31;
    const int g    = li >> 2;      // 0..7
    const int q    = li & 3;       // 0..3
    const int w16  = w * 16;

    // ---- stage X (hi/lo tf32) + kb + pb ----
    {
        const float4* gx =
            (const float4*)(x + ((size_t)b * NQ + (size_t)tile * 64) * C);
        #pragma unroll
        for (int n = 0; n < 8; n++) {
            int e = t + n * 128;
            int row = e >> 4, kq = e & 15;
            float4 v = gx[e];
            uint4 hb, lb;
            hb.x = f2tf(v.x); lb.x = f2tf(v.x - __uint_as_float(hb.x));
            hb.y = f2tf(v.y); lb.y = f2tf(v.y - __uint_as_float(hb.y));
            hb.z = f2tf(v.z); lb.z = f2tf(v.z - __uint_as_float(hb.z));
            hb.w = f2tf(v.w); lb.w = f2tf(v.w - __uint_as_float(hb.w));
            *(uint4*)&uXH[row * 68 + kq * 4] = hb;
            *(uint4*)&uXL[row * 68 + kq * 4] = lb;
        }
        sm[AS_KB + t]       = g_kb[b * NR + t];
        sm[AS_KB + t + 128] = g_kb[b * NR + t + 128];
        if (t < 64) sm[AS_PB + t] = proj_b[t];
    }

    float o[8][4];
    #pragma unroll
    for (int i = 0; i < 8; i++)
        #pragma unroll
        for (int j = 0; j < 4; j++) o[i][j] = 0.f;
    float dl = 0.f, dh = 0.f;

    const float* gktB = g_KtT + (size_t)b * C * NR;
    const float* gwB  = g_Wv + (size_t)b * NR * C;

    #pragma unroll 1
    for (int c = 0; c < 4; c++) {
        // ---- stage Kt chunk [64k][64j] + Wv chunk [64j][64ch], hi/lo ----
        #pragma unroll
        for (int n = 0; n < 8; n++) {
            int e = t + n * 128;
            int r = e >> 4, cb = e & 15;
            float4 kv = *(const float4*)(gktB + r * 256 + c * 64 + cb * 4);
            uint4 hb, lb;
            hb.x = f2tf(kv.x); lb.x = f2tf(kv.x - __uint_as_float(hb.x));
            hb.y = f2tf(kv.y); lb.y = f2tf(kv.y - __uint_as_float(hb.y));
            hb.z = f2tf(kv.z); lb.z = f2tf(kv.z - __uint_as_float(hb.z));
            hb.w = f2tf(kv.w); lb.w = f2tf(kv.w - __uint_as_float(hb.w));
            *(uint4*)&uKH[r * 72 + cb * 4] = hb;
            *(uint4*)&uKL[r * 72 + cb * 4] = lb;
            float4 wv = *(const float4*)(gwB + ((size_t)c * 64 + r) * 64 + cb * 4);
            uint4 whb, wlb;
            whb.x = f2tf(wv.x); wlb.x = f2tf(wv.x - __uint_as_float(whb.x));
            whb.y = f2tf(wv.y); wlb.y = f2tf(wv.y - __uint_as_float(whb.y));
            whb.z = f2tf(wv.z); wlb.z = f2tf(wv.z - __uint_as_float(whb.z));
            whb.w = f2tf(wv.w); wlb.w = f2tf(wv.w - __uint_as_float(whb.w));
            *(uint4*)&uWH[r * 72 + cb * 4] = whb;
            *(uint4*)&uWL[r * 72 + cb * 4] = wlb;
        }
        __syncthreads();

        // ===== pass 1: S[16][64] = X @ Kt^T  (tf32x3) =====
        float sc[8][4];
        #pragma unroll
        for (int i = 0; i < 8; i++)
            #pragma unroll
            for (int j = 0; j < 4; j++) sc[i][j] = 0.f;

        #pragma unroll
        for (int ks = 0; ks < 8; ks++) {
            uint32_t ah[4], al[4];
            int xb = (w16 + g) * 68 + ks * 8 + q;
            ah[0] = uXH[xb];           al[0] = uXL[xb];
            ah[1] = uXH[xb + 8 * 68];  al[1] = uXL[xb + 8 * 68];
            ah[2] = uXH[xb + 4];       al[2] = uXL[xb + 4];
            ah[3] = uXH[xb + 8 * 68 + 4]; al[3] = uXL[xb + 8 * 68 + 4];
            #pragma unroll
            for (int nt = 0; nt < 8; nt++) {
                int bb = (ks * 8 + q) * 72 + nt * 8 + g;
                uint32_t bh0 = uKH[bb], bh1 = uKH[bb + 4 * 72];
                uint32_t bl0 = uKL[bb], bl1 = uKL[bb + 4 * 72];
                mma8(sc[nt], ah, bh0, bh1);
                mma8(sc[nt], al, bh0, bh1);
                mma8(sc[nt], ah, bl0, bl1);
            }
        }
        __syncthreads();  // Kt reads done before P overwrites the buffers

        // ---- exp + kb, accumulate den, split P hi/lo, store ----
        #pragma unroll
        for (int nt = 0; nt < 8; nt++) {
            int jc = c * 64 + nt * 8 + 2 * q;
            float kb0 = sm[AS_KB + jc], kb1 = sm[AS_KB + jc + 1];
            float e00 = __expf(sc[nt][0] + kb0);
            float e01 = __expf(sc[nt][1] + kb1);
            float e10 = __expf(sc[nt][2] + kb0);
            float e11 = __expf(sc[nt][3] + kb1);
            dl += e00 + e01;
            dh += e10 + e11;
            uint2 ph, pl;
            int pa = (w16 + g) * 68 + nt * 8 + 2 * q;
            ph.x = f2tf(e00); pl.x = f2tf(e00 - __uint_as_float(ph.x));
            ph.y = f2tf(e01); pl.y = f2tf(e01 - __uint_as_float(ph.y));
            *(uint2*)&uPH[pa] = ph;
            *(uint2*)&uPL[pa] = pl;
            int pa2 = (w16 + g + 8) * 68 + nt * 8 + 2 * q;
            ph.x = f2tf(e10); pl.x = f2tf(e10 - __uint_as_float(ph.x));
            ph.y = f2tf(e11); pl.y = f2tf(e11 - __uint_as_float(ph.y));
            *(uint2*)&uPH[pa2] = ph;
            *(uint2*)&uPL[pa2] = pl;
        }
        __syncthreads();  // P visible

        // ===== pass 2: O[16][64] += P @ Wv  (tf32x3) =====
        #pragma unroll
        for (int ks = 0; ks < 8; ks++) {
            uint32_t ah[4], al[4];
            int pb = (w16 + g) * 68 + ks * 8 + q;
            ah[0] = uPH[pb];           al[0] = uPL[pb];
            ah[1] = uPH[pb + 8 * 68];  al[1] = uPL[pb + 8 * 68];
            ah[2] = uPH[pb + 4];       al[2] = uPL[pb + 4];
            ah[3] = uPH[pb + 8 * 68 + 4]; al[3] = uPL[pb + 8 * 68 + 4];
            #pragma unroll
            for (int nt = 0; nt < 8; nt++) {
                int bb = (ks * 8 + q) * 72 + nt * 8 + g;
                uint32_t bh0 = uWH[bb], bh1 = uWH[bb + 4 * 72];
                uint32_t bl0 = uWL[bb], bl1 = uWL[bb + 4 * 72];
                mma8(o[nt], ah, bh0, bh1);
                mma8(o[nt], al, bh0, bh1);
                mma8(o[nt], ah, bl0, bl1);
            }
        }
        __syncthreads();  // buffers reused next chunk
    }

    // ---- den: reduce over q within each g-quad, publish ----
    dl += __shfl_xor_sync(0xffffffffu, dl, 1);
    dl += __shfl_xor_sync(0xffffffffu, dl, 2);
    dh += __shfl_xor_sync(0xffffffffu, dh, 1);
    dh += __shfl_xor_sync(0xffffffffu, dh, 2);
    if (q == 0) {
        sm[AS_DEN + w16 + g]     = dl;
        sm[AS_DEN + w16 + g + 8] = dh;
    }
    __syncthreads();

    // ---- epilogue: out = O/den + proj_b ----
    float inv0 = 1.0f / sm[AS_DEN + w16 + g];
    float inv1 = 1.0f / sm[AS_DEN + w16 + g + 8];
    size_t r0 = (size_t)b * NQ + (size_t)tile * 64 + w16 + g;
    #pragma unroll
    for (int nt = 0; nt < 8; nt++) {
        int ch = nt * 8 + 2 * q;
        float pb0 = sm[AS_PB + ch], pb1 = sm[AS_PB + ch + 1];
        float2 v0;
        v0.x = fmaf(o[nt][0], inv0, pb0);
        v0.y = fmaf(o[nt][1], inv0, pb1);
        *(float2*)&out[r0 * 64 + ch] = v0;
        float2 v1;
        v1.x = fmaf(o[nt][2], inv1, pb0);
        v1.y = fmaf(o[nt][3], inv1, pb1);
        *(float2*)&out[(r0 + 8) * 64 + ch] = v1;
    }
}

// ---------------------------------------------------------------------------
extern "C" void kernel_launch(void* const* d_in, const int* in_sizes, int n_in,
                              void* d_out, int out_size) {
    const float* x      = (const float*)d_in[0];
    const float* sr_w   = (const float*)d_in[1];
    const float* sr_b   = (const float*)d_in[2];
    const float* ln_g   = (const float*)d_in[3];
    const float* ln_b   = (const float*)d_in[4];
    const float* q_w    = (const float*)d_in[5];
    const float* q_b    = (const float*)d_in[6];
    const float* kv_w   = (const float*)d_in[7];
    const float* kv_b   = (const float*)d_in[8];
    const float* proj_w = (const float*)d_in[9];
    const float* proj_b = (const float*)d_in[10];
    float* out = (float*)d_out;

    static bool attr_set = false;
    if (!attr_set) {
        cudaFuncSetAttribute(attn_kernel,
                             cudaFuncAttributeMaxDynamicSharedMemorySize,
                             ATTN_SMEM_BYTES);
        attr_set = true;
    }

    prep_w_kernel<<<256, 1024>>>(sr_w);
    prep_t_kernel<<<8, 1024>>>(kv_w, proj_w);
    conv_kernel<<<dim3(16, 8), 256>>>(x, sr_b);
    ln_fold_kernel<<<512, 256>>>(ln_g, ln_b, q_w, q_b, kv_b);
    attn_kernel<<<dim3(256, 8), 128, ATTN_SMEM_BYTES>>>(x, proj_b, out);
}